// round 9
// baseline (speedup 1.0000x reference)
#include <cuda_runtime.h>
#include <cuda.h>
#include <cuda_fp16.h>
#include <math.h>
#include <stdint.h>

// ---------------------------------------------------------------------------
// Problem constants
// ---------------------------------------------------------------------------
#define B_    4
#define T_    2048
#define C_    1024
#define H_    16
#define D_    64
#define M_    (B_ * T_)        // 8192
#define N_QKV (3 * C_)         // 3072

// Scratch (__device__ globals; allocation-free rule)
__device__ __half g_hx[M_ * C_];
__device__ __half g_hw1[N_QKV * C_];
__device__ __half g_hw2[C_ * C_];
__device__ __half g_qkv[(size_t)M_ * N_QKV];
__device__ __half g_att[M_ * C_];

// ---------------------------------------------------------------------------
// PTX helpers
// ---------------------------------------------------------------------------
__device__ __forceinline__ unsigned sptr(const void* p) {
    return (unsigned)__cvta_generic_to_shared(p);
}
__device__ __forceinline__ void ldsm4(unsigned& r0, unsigned& r1,
                                      unsigned& r2, unsigned& r3, unsigned a) {
    asm volatile("ldmatrix.sync.aligned.m8n8.x4.shared.b16 {%0,%1,%2,%3},[%4];"
                 : "=r"(r0), "=r"(r1), "=r"(r2), "=r"(r3) : "r"(a));
}
__device__ __forceinline__ void ldsm4t(unsigned& r0, unsigned& r1,
                                       unsigned& r2, unsigned& r3, unsigned a) {
    asm volatile("ldmatrix.sync.aligned.m8n8.x4.trans.shared.b16 {%0,%1,%2,%3},[%4];"
                 : "=r"(r0), "=r"(r1), "=r"(r2), "=r"(r3) : "r"(a));
}
__device__ __forceinline__ void mma16816(float* d,
                                         unsigned a0, unsigned a1, unsigned a2, unsigned a3,
                                         unsigned b0, unsigned b1) {
    asm volatile(
        "mma.sync.aligned.m16n8k16.row.col.f32.f16.f16.f32 "
        "{%0,%1,%2,%3},{%4,%5,%6,%7},{%8,%9},{%0,%1,%2,%3};"
        : "+f"(d[0]), "+f"(d[1]), "+f"(d[2]), "+f"(d[3])
        : "r"(a0), "r"(a1), "r"(a2), "r"(a3), "r"(b0), "r"(b1));
}
__device__ __forceinline__ void mbar_init(unsigned a, unsigned cnt) {
    asm volatile("mbarrier.init.shared.b64 [%0], %1;" :: "r"(a), "r"(cnt) : "memory");
}
__device__ __forceinline__ void mbar_expect(unsigned a, unsigned bytes) {
    asm volatile("mbarrier.arrive.expect_tx.shared.b64 _, [%0], %1;"
                 :: "r"(a), "r"(bytes) : "memory");
}
__device__ __forceinline__ void mbar_wait(unsigned a, unsigned parity) {
    asm volatile(
        "{\n\t.reg .pred P;\n\t"
        "W%=:\n\t"
        "mbarrier.try_wait.parity.acquire.cta.shared::cta.b64 P, [%0], %1, 0x989680;\n\t"
        "@P bra.uni D%=;\n\t"
        "bra.uni W%=;\n\t"
        "D%=:\n\t}"
        :: "r"(a), "r"(parity) : "memory");
}
__device__ __forceinline__ void tma3d(unsigned dst, const void* tm, int x, int y, unsigned mbar) {
    asm volatile(
        "cp.async.bulk.tensor.3d.shared::cta.global.tile.mbarrier::complete_tx::bytes "
        "[%0], [%1, {%2, %3, %4}], [%5];"
        :: "r"(dst), "l"(tm), "r"(x), "r"(y), "r"(0), "r"(mbar) : "memory");
}
__device__ __forceinline__ void fence_async_shared() {
    asm volatile("fence.proxy.async.shared::cta;" ::: "memory");
}

// ---------------------------------------------------------------------------
// fp32 -> fp16 convert
// ---------------------------------------------------------------------------
__global__ void f2h_kernel(const float* __restrict__ in, __half* __restrict__ out, int n4) {
    int i = blockIdx.x * blockDim.x + threadIdx.x;
    if (i < n4) {
        float4 v = ((const float4*)in)[i];
        __half2 h0 = __floats2half2_rn(v.x, v.y);
        __half2 h1 = __floats2half2_rn(v.z, v.w);
        uint2 u;
        u.x = *(unsigned*)&h0;
        u.y = *(unsigned*)&h1;
        ((uint2*)out)[i] = u;
    }
}

// ---------------------------------------------------------------------------
// TMA-fed HMMA GEMM (proven round 8, unchanged).
// ---------------------------------------------------------------------------
#define NSTAGE   3
#define ABYTES   (128 * 64 * 2)
#define STAGEB   (2 * ABYTES)
#define NKCHUNK  16
#define GEMM_DSMEM (NSTAGE * STAGEB + 1024)

template <bool HALF_OUT>
__global__ __launch_bounds__(256, 2)
void gemm_tma_kernel(const __grid_constant__ CUtensorMap tmA,
                     const __grid_constant__ CUtensorMap tmW,
                     const float* __restrict__ bias,
                     void* __restrict__ Cc, int N)
{
    extern __shared__ char dsm_raw[];
    __shared__ __align__(8) unsigned long long s_mbar[NSTAGE];

    char* smb = (char*)(((uintptr_t)dsm_raw + 1023) & ~(uintptr_t)1023);
    const unsigned base = sptr(smb);

    const int tid  = threadIdx.x;
    const int warp = tid >> 5;
    const int lane = tid & 31;
    const int wm   = warp & 3;
    const int wn   = warp >> 2;
    const int g    = lane >> 2;
    const int q    = lane & 3;
    const int la   = lane & 7;
    const int lb   = (lane >> 3) & 1;
    const int lc   = lane >> 4;
    const int bm   = blockIdx.y * 128;
    const int bn   = blockIdx.x * 128;

    unsigned mf[NSTAGE];
#pragma unroll
    for (int s = 0; s < NSTAGE; s++) mf[s] = sptr(&s_mbar[s]);

    if (tid == 0)
#pragma unroll
        for (int s = 0; s < NSTAGE; s++) mbar_init(mf[s], 1);
    __syncthreads();

    if (tid == 0) {
#pragma unroll
        for (int s = 0; s < NSTAGE; s++) {
            mbar_expect(mf[s], STAGEB);
            tma3d(base + s * STAGEB,          &tmA, s * 64, bm, mf[s]);
            tma3d(base + s * STAGEB + ABYTES, &tmW, s * 64, bn, mf[s]);
        }
    }

    float acc[2][8][4];
#pragma unroll
    for (int mt = 0; mt < 2; mt++)
#pragma unroll
        for (int nt = 0; nt < 8; nt++)
#pragma unroll
            for (int c = 0; c < 4; c++) acc[mt][nt][c] = 0.0f;

    for (int c = 0; c < NKCHUNK; c++) {
        const int s = c % NSTAGE;
        const unsigned ph = (unsigned)((c / NSTAGE) & 1);
        mbar_wait(mf[s], ph);

        const unsigned abase = base + s * STAGEB;
        const unsigned bbase = abase + ABYTES;

#pragma unroll
        for (int kk = 0; kk < 4; kk++) {
            unsigned a[2][4];
#pragma unroll
            for (int mt = 0; mt < 2; mt++) {
                int row = wm * 32 + mt * 16 + lb * 8 + la;
                int ch  = (2 * kk + lc) ^ (row & 7);
                ldsm4(a[mt][0], a[mt][1], a[mt][2], a[mt][3],
                      abase + row * 128 + ch * 16);
            }
            unsigned bfr[4][4];
#pragma unroll
            for (int ntp = 0; ntp < 4; ntp++) {
                int row = wn * 64 + ntp * 16 + lc * 8 + la;
                int ch  = (2 * kk + lb) ^ (row & 7);
                ldsm4(bfr[ntp][0], bfr[ntp][1], bfr[ntp][2], bfr[ntp][3],
                      bbase + row * 128 + ch * 16);
            }
#pragma unroll
            for (int mt = 0; mt < 2; mt++)
#pragma unroll
                for (int ntp = 0; ntp < 4; ntp++) {
                    mma16816(acc[mt][2 * ntp],     a[mt][0], a[mt][1], a[mt][2], a[mt][3],
                             bfr[ntp][0], bfr[ntp][1]);
                    mma16816(acc[mt][2 * ntp + 1], a[mt][0], a[mt][1], a[mt][2], a[mt][3],
                             bfr[ntp][2], bfr[ntp][3]);
                }
        }

        __syncthreads();

        if (tid == 0) {
            const int cn = c + NSTAGE;
            if (cn < NKCHUNK) {
                fence_async_shared();
                mbar_expect(mf[s], STAGEB);
                tma3d(abase, &tmA, cn * 64, bm, mf[s]);
                tma3d(bbase, &tmW, cn * 64, bn, mf[s]);
            }
        }
    }

    float2 bv[8];
#pragma unroll
    for (int nt = 0; nt < 8; nt++) {
        int col = bn + wn * 64 + nt * 8 + 2 * q;
        bv[nt].x = bias[col];
        bv[nt].y = bias[col + 1];
    }
#pragma unroll
    for (int mt = 0; mt < 2; mt++) {
        int row = bm + wm * 32 + mt * 16 + g;
#pragma unroll
        for (int nt = 0; nt < 8; nt++) {
            int col = bn + wn * 64 + nt * 8 + 2 * q;
            float x0 = acc[mt][nt][0] + bv[nt].x;
            float y0 = acc[mt][nt][1] + bv[nt].y;
            float x1 = acc[mt][nt][2] + bv[nt].x;
            float y1 = acc[mt][nt][3] + bv[nt].y;
            if (HALF_OUT) {
                __half* O = (__half*)Cc;
                *(__half2*)&O[(size_t)row * N + col]       = __floats2half2_rn(x0, y0);
                *(__half2*)&O[(size_t)(row + 8) * N + col] = __floats2half2_rn(x1, y1);
            } else {
                float* O = (float*)Cc;
                *(float2*)&O[(size_t)row * N + col]       = make_float2(x0, y0);
                *(float2*)&O[(size_t)(row + 8) * N + col] = make_float2(x1, y1);
            }
        }
    }
}

// ---------------------------------------------------------------------------
// Flash attention: BQ=128, BK=64, 512 threads (16 warps: 8 m x 2 n).
// Double-buffered TMA K/V (SW128, 1024-aligned buffers first in dyn smem).
// Layout: K0 K1 V0 V1 (8 KB each) | Qs[128*72] | Ps[128*72]
// ---------------------------------------------------------------------------
#define FSTR 72
#define FL_TILEB  (64 * 64 * 2)                        // 8 KB
#define FL_QB     (128 * FSTR * 2)                     // 18 KB
#define FL_DSMEM  (4 * FL_TILEB + 2 * FL_QB + 1024)

__global__ __launch_bounds__(512, 1)
void flash_f16_kernel(const __grid_constant__ CUtensorMap tmKV,
                      const __half* __restrict__ qkv, __half* __restrict__ out)
{
    extern __shared__ char fraw[];
    __shared__ float redmax[256];
    __shared__ float redsum[256];
    __shared__ __align__(8) unsigned long long s_fm[2];

    char* fb = (char*)(((uintptr_t)fraw + 1023) & ~(uintptr_t)1023);
    const unsigned base = sptr(fb);
    const unsigned kbuf[2] = {base,               base + FL_TILEB};
    const unsigned vbuf[2] = {base + 2 * FL_TILEB, base + 3 * FL_TILEB};
    __half* Qs = (__half*)(fb + 4 * FL_TILEB);
    __half* Ps = Qs + 128 * FSTR;
    const unsigned qsb = sptr(Qs);
    const unsigned psb = sptr(Ps);
    const unsigned fm[2] = {sptr(&s_fm[0]), sptr(&s_fm[1])};

    const int qt   = (int)gridDim.x - 1 - (int)blockIdx.x;  // heavy tiles first
    const int bh   = blockIdx.y;
    const int bb   = bh >> 4;
    const int h    = bh & 15;
    const int tid  = threadIdx.x;
    const int warp = tid >> 5;
    const int lane = tid & 31;
    const int wm   = warp >> 1;    // 0..7 (16 q-rows each)
    const int wn   = warp & 1;     // 0..1 (32 s-cols each)
    const int g    = lane >> 2;
    const int q    = lane & 3;
    const int la   = lane & 7;
    const int lb   = (lane >> 3) & 1;
    const int lc   = lane >> 4;
    const int r0   = wm * 16 + g;
    const int r1   = r0 + 8;

    if (tid == 0) {
        mbar_init(fm[0], 1);
        mbar_init(fm[1], 1);
    }

    // Load Q tile 128x64 (scaled by 1/8, exact in fp16), padded stride 72
    const __half* qb = qkv + (size_t)(bb * T_) * N_QKV + h * D_;
    const __half2 hs = __floats2half2_rn(0.125f, 0.125f);
#pragma unroll
    for (int i = 0; i < 2; i++) {
        int idx = tid + i * 512;           // 0..1023 uint4 units
        int r   = idx >> 3;                // 0..127
        int c8  = idx & 7;                 // 0..7
        uint4 v = *(const uint4*)(qb + (size_t)(qt * 128 + r) * N_QKV + 8 * c8);
        __half2* p = (__half2*)&v;
        p[0] = __hmul2(p[0], hs); p[1] = __hmul2(p[1], hs);
        p[2] = __hmul2(p[2], hs); p[3] = __hmul2(p[3], hs);
        *(uint4*)&Qs[r * FSTR + 8 * c8] = v;
    }
    __syncthreads();   // mbar init + Q stores visible

    if (tid == 0) {
        mbar_expect(fm[0], 2 * FL_TILEB);
        tma3d(kbuf[0], &tmKV, C_ + h * 64,     bb * T_ + qt * 0, fm[0]);
        tma3d(vbuf[0], &tmKV, 2 * C_ + h * 64, bb * T_ + qt * 0, fm[0]);
    }

    float o[4][4];
#pragma unroll
    for (int j = 0; j < 4; j++)
#pragma unroll
        for (int c = 0; c < 4; c++) o[j][c] = 0.0f;
    float m0 = -1e30f, m1 = -1e30f, l0 = 0.0f, l1 = 0.0f;

    const int nkt = 2 * qt + 1;            // last kt index
    const int growbase = qt * 128;

    for (int kt = 0; kt <= nkt; kt++) {
        const int buf = kt & 1;
        mbar_wait(fm[buf], (unsigned)((kt >> 1) & 1));

        // S = Q K^T  (Q padded; K SW128-swizzled)
        float s[4][4];
#pragma unroll
        for (int j = 0; j < 4; j++)
#pragma unroll
            for (int c = 0; c < 4; c++) s[j][c] = 0.0f;

#pragma unroll
        for (int kk = 0; kk < 4; kk++) {
            unsigned a0, a1, a2, a3;
            {
                int row = wm * 16 + lb * 8 + la;
                int ch  = 2 * kk + lc;
                ldsm4(a0, a1, a2, a3, qsb + (row * FSTR + ch * 8) * 2);
            }
#pragma unroll
            for (int ntp = 0; ntp < 2; ntp++) {
                unsigned b0, b1, b2, b3;
                int row = wn * 32 + ntp * 16 + lc * 8 + la;
                int ch  = (2 * kk + lb) ^ (row & 7);
                ldsm4(b0, b1, b2, b3, kbuf[buf] + row * 128 + ch * 16);
                mma16816(s[2 * ntp],     a0, a1, a2, a3, b0, b1);
                mma16816(s[2 * ntp + 1], a0, a1, a2, a3, b2, b3);
            }
        }

        // Causal mask (only the last two K tiles can cross the diagonal)
        if (kt >= 2 * qt) {
            const int gc0 = kt * 64;
#pragma unroll
            for (int j = 0; j < 4; j++) {
                int c = gc0 + wn * 32 + j * 8 + 2 * q;
                if (c     > growbase + r0) s[j][0] = -1e30f;
                if (c + 1 > growbase + r0) s[j][1] = -1e30f;
                if (c     > growbase + r1) s[j][2] = -1e30f;
                if (c + 1 > growbase + r1) s[j][3] = -1e30f;
            }
        }

        float mx0 = -1e30f, mx1 = -1e30f;
#pragma unroll
        for (int j = 0; j < 4; j++) {
            mx0 = fmaxf(mx0, fmaxf(s[j][0], s[j][1]));
            mx1 = fmaxf(mx1, fmaxf(s[j][2], s[j][3]));
        }
        mx0 = fmaxf(mx0, __shfl_xor_sync(0xffffffffu, mx0, 1));
        mx0 = fmaxf(mx0, __shfl_xor_sync(0xffffffffu, mx0, 2));
        mx1 = fmaxf(mx1, __shfl_xor_sync(0xffffffffu, mx1, 1));
        mx1 = fmaxf(mx1, __shfl_xor_sync(0xffffffffu, mx1, 2));
        if (q == 0) {
            redmax[wn * 128 + r0] = mx0;
            redmax[wn * 128 + r1] = mx1;
        }
        __syncthreads();   // also: all reads of buf^1 from iter kt-1 are done

        // Prefetch kt+1 into the other buffer
        if (tid == 0 && kt < nkt) {
            fence_async_shared();
            const int nb = buf ^ 1;
            mbar_expect(fm[nb], 2 * FL_TILEB);
            tma3d(kbuf[nb], &tmKV, C_ + h * 64,     bb * T_ + (kt + 1) * 64, fm[nb]);
            tma3d(vbuf[nb], &tmKV, 2 * C_ + h * 64, bb * T_ + (kt + 1) * 64, fm[nb]);
        }

        float mn0 = fmaxf(m0, fmaxf(redmax[r0], redmax[128 + r0]));
        float mn1 = fmaxf(m1, fmaxf(redmax[r1], redmax[128 + r1]));
        float cr0 = __expf(m0 - mn0);
        float cr1 = __expf(m1 - mn1);
        m0 = mn0; m1 = mn1;

        float sum0 = 0.0f, sum1 = 0.0f;
#pragma unroll
        for (int j = 0; j < 4; j++) {
            int c = wn * 32 + j * 8 + 2 * q;
            float p0 = __expf(s[j][0] - mn0);
            float p1 = __expf(s[j][1] - mn0);
            float p2 = __expf(s[j][2] - mn1);
            float p3 = __expf(s[j][3] - mn1);
            sum0 += p0 + p1;
            sum1 += p2 + p3;
            *(__half2*)&Ps[r0 * FSTR + c] = __floats2half2_rn(p0, p1);
            *(__half2*)&Ps[r1 * FSTR + c] = __floats2half2_rn(p2, p3);
        }
        sum0 += __shfl_xor_sync(0xffffffffu, sum0, 1);
        sum0 += __shfl_xor_sync(0xffffffffu, sum0, 2);
        sum1 += __shfl_xor_sync(0xffffffffu, sum1, 1);
        sum1 += __shfl_xor_sync(0xffffffffu, sum1, 2);
        if (q == 0) {
            redsum[wn * 128 + r0] = sum0;
            redsum[wn * 128 + r1] = sum1;
        }

#pragma unroll
        for (int j = 0; j < 4; j++) {
            o[j][0] *= cr0; o[j][1] *= cr0;
            o[j][2] *= cr1; o[j][3] *= cr1;
        }
        __syncthreads();   // Ps writes + redsum visible

        l0 = l0 * cr0 + redsum[r0] + redsum[128 + r0];
        l1 = l1 * cr1 + redsum[r1] + redsum[128 + r1];

        // O += P V   (P padded; V SW128-swizzled, transposed ldmatrix)
#pragma unroll
        for (int kkv = 0; kkv < 4; kkv++) {
            unsigned a0, a1, a2, a3;
            {
                int row = wm * 16 + lb * 8 + la;
                int ch  = 2 * kkv + lc;
                ldsm4(a0, a1, a2, a3, psb + (row * FSTR + ch * 8) * 2);
            }
#pragma unroll
            for (int ntp = 0; ntp < 2; ntp++) {
                unsigned b0, b1, b2, b3;
                int row = kkv * 16 + lb * 8 + la;
                int ch  = (4 * wn + 2 * ntp + lc) ^ (row & 7);
                ldsm4t(b0, b1, b2, b3, vbuf[buf] + row * 128 + ch * 16);
                mma16816(o[2 * ntp],     a0, a1, a2, a3, b0, b1);
                mma16816(o[2 * ntp + 1], a0, a1, a2, a3, b2, b3);
            }
        }
    }

    float il0 = 1.0f / l0;
    float il1 = 1.0f / l1;
    size_t row0 = (size_t)(bb * T_ + qt * 128 + r0);
    size_t row1 = (size_t)(bb * T_ + qt * 128 + r1);
#pragma unroll
    for (int j = 0; j < 4; j++) {
        int col = h * 64 + wn * 32 + j * 8 + 2 * q;
        *(__half2*)&out[row0 * C_ + col] = __floats2half2_rn(o[j][0] * il0, o[j][1] * il0);
        *(__half2*)&out[row1 * C_ + col] = __floats2half2_rn(o[j][2] * il1, o[j][3] * il1);
    }
}

// ---------------------------------------------------------------------------
// Host: tensormaps + launch
// ---------------------------------------------------------------------------
typedef CUresult (*PFN_encode)(CUtensorMap*, CUtensorMapDataType, cuuint32_t, void*,
                               const cuuint64_t*, const cuuint64_t*, const cuuint32_t*,
                               const cuuint32_t*, CUtensorMapInterleave, CUtensorMapSwizzle,
                               CUtensorMapL2promotion, CUtensorMapFloatOOBfill);

static void make_map(PFN_encode enc, CUtensorMap* tm, void* ptr,
                     unsigned long long cols, unsigned long long rows,
                     unsigned bx, unsigned by) {
    cuuint64_t dims[3]    = {cols, rows, 1};
    cuuint64_t strides[2] = {cols * 2, rows * cols * 2};
    cuuint32_t box[3]     = {bx, by, 1};
    cuuint32_t es[3]      = {1, 1, 1};
    enc(tm, CU_TENSOR_MAP_DATA_TYPE_FLOAT16, 3, ptr, dims, strides, box, es,
        CU_TENSOR_MAP_INTERLEAVE_NONE, CU_TENSOR_MAP_SWIZZLE_128B,
        CU_TENSOR_MAP_L2_PROMOTION_L2_128B, CU_TENSOR_MAP_FLOAT_OOB_FILL_NONE);
}

extern "C" void kernel_launch(void* const* d_in, const int* in_sizes, int n_in,
                              void* d_out, int out_size)
{
    const float* x      = (const float*)d_in[0];
    const float* W_qkv  = (const float*)d_in[1];
    const float* b_qkv  = (const float*)d_in[2];
    const float* W_proj = (const float*)d_in[3];
    const float* b_proj = (const float*)d_in[4];
    float* out = (float*)d_out;

    __half *hx, *hw1, *hw2, *qkv, *att;
    cudaGetSymbolAddress((void**)&hx,  g_hx);
    cudaGetSymbolAddress((void**)&hw1, g_hw1);
    cudaGetSymbolAddress((void**)&hw2, g_hw2);
    cudaGetSymbolAddress((void**)&qkv, g_qkv);
    cudaGetSymbolAddress((void**)&att, g_att);

    void* fnp = nullptr;
    cudaDriverEntryPointQueryResult qr;
    cudaGetDriverEntryPointByVersion("cuTensorMapEncodeTiled", &fnp, 12000,
                                     cudaEnableDefault, &qr);
    PFN_encode enc = (PFN_encode)fnp;

    CUtensorMap tmX, tmW1, tmAtt, tmW2, tmKV;
    make_map(enc, &tmX,   hx,  C_,    M_,    64, 128);
    make_map(enc, &tmW1,  hw1, C_,    N_QKV, 64, 128);
    make_map(enc, &tmAtt, att, C_,    M_,    64, 128);
    make_map(enc, &tmW2,  hw2, C_,    C_,    64, 128);
    make_map(enc, &tmKV,  qkv, N_QKV, M_,    64, 64);

    // 0) fp32 -> fp16 converts
    f2h_kernel<<<(M_ * C_ / 4 + 255) / 256, 256>>>(x, hx, M_ * C_ / 4);
    f2h_kernel<<<(N_QKV * C_ / 4 + 255) / 256, 256>>>(W_qkv, hw1, N_QKV * C_ / 4);
    f2h_kernel<<<(C_ * C_ / 4 + 255) / 256, 256>>>(W_proj, hw2, C_ * C_ / 4);

    // 1) qkv = x @ W_qkv^T + b_qkv (half out)
    cudaFuncSetAttribute((const void*)gemm_tma_kernel<true>,
                         cudaFuncAttributeMaxDynamicSharedMemorySize, GEMM_DSMEM);
    gemm_tma_kernel<true><<<dim3(N_QKV / 128, M_ / 128), 256, GEMM_DSMEM>>>(
        tmX, tmW1, b_qkv, qkv, N_QKV);

    // 2) flash attention (BQ=128, 512 threads, double-buffered TMA K/V)
    cudaFuncSetAttribute(flash_f16_kernel,
                         cudaFuncAttributeMaxDynamicSharedMemorySize, FL_DSMEM);
    flash_f16_kernel<<<dim3(T_ / 128, B_ * H_), 512, FL_DSMEM>>>(tmKV, qkv, att);

    // 3) out = att @ W_proj^T + b_proj (float out)
    cudaFuncSetAttribute((const void*)gemm_tma_kernel<false>,
                         cudaFuncAttributeMaxDynamicSharedMemorySize, GEMM_DSMEM);
    gemm_tma_kernel<false><<<dim3(C_ / 128, M_ / 128), 256, GEMM_DSMEM>>>(
        tmAtt, tmW2, b_proj, out, C_);
}

// round 10
// speedup vs baseline: 1.2735x; 1.2735x over previous
#include <cuda_runtime.h>
#include <cuda.h>
#include <cuda_fp16.h>
#include <math.h>
#include <stdint.h>

// ---------------------------------------------------------------------------
// Problem constants
// ---------------------------------------------------------------------------
#define B_    4
#define T_    2048
#define C_    1024
#define H_    16
#define D_    64
#define M_    (B_ * T_)        // 8192
#define N_QKV (3 * C_)         // 3072

// Scratch (__device__ globals; allocation-free rule)
__device__ __half g_hx[M_ * C_];
__device__ __half g_hw1[N_QKV * C_];
__device__ __half g_hw2[C_ * C_];
__device__ __half g_qkv[(size_t)M_ * N_QKV];
__device__ __half g_att[M_ * C_];

// ---------------------------------------------------------------------------
// PTX helpers
// ---------------------------------------------------------------------------
__device__ __forceinline__ unsigned sptr(const void* p) {
    return (unsigned)__cvta_generic_to_shared(p);
}
__device__ __forceinline__ void ldsm4(unsigned& r0, unsigned& r1,
                                      unsigned& r2, unsigned& r3, unsigned a) {
    asm volatile("ldmatrix.sync.aligned.m8n8.x4.shared.b16 {%0,%1,%2,%3},[%4];"
                 : "=r"(r0), "=r"(r1), "=r"(r2), "=r"(r3) : "r"(a));
}
__device__ __forceinline__ void ldsm4t(unsigned& r0, unsigned& r1,
                                       unsigned& r2, unsigned& r3, unsigned a) {
    asm volatile("ldmatrix.sync.aligned.m8n8.x4.trans.shared.b16 {%0,%1,%2,%3},[%4];"
                 : "=r"(r0), "=r"(r1), "=r"(r2), "=r"(r3) : "r"(a));
}
__device__ __forceinline__ void mma16816(float* d,
                                         unsigned a0, unsigned a1, unsigned a2, unsigned a3,
                                         unsigned b0, unsigned b1) {
    asm volatile(
        "mma.sync.aligned.m16n8k16.row.col.f32.f16.f16.f32 "
        "{%0,%1,%2,%3},{%4,%5,%6,%7},{%8,%9},{%0,%1,%2,%3};"
        : "+f"(d[0]), "+f"(d[1]), "+f"(d[2]), "+f"(d[3])
        : "r"(a0), "r"(a1), "r"(a2), "r"(a3), "r"(b0), "r"(b1));
}
__device__ __forceinline__ void mbar_init(unsigned a, unsigned cnt) {
    asm volatile("mbarrier.init.shared.b64 [%0], %1;" :: "r"(a), "r"(cnt) : "memory");
}
__device__ __forceinline__ void mbar_expect(unsigned a, unsigned bytes) {
    asm volatile("mbarrier.arrive.expect_tx.shared.b64 _, [%0], %1;"
                 :: "r"(a), "r"(bytes) : "memory");
}
__device__ __forceinline__ void mbar_wait(unsigned a, unsigned parity) {
    asm volatile(
        "{\n\t.reg .pred P;\n\t"
        "W%=:\n\t"
        "mbarrier.try_wait.parity.acquire.cta.shared::cta.b64 P, [%0], %1, 0x989680;\n\t"
        "@P bra.uni D%=;\n\t"
        "bra.uni W%=;\n\t"
        "D%=:\n\t}"
        :: "r"(a), "r"(parity) : "memory");
}
__device__ __forceinline__ void tma3d(unsigned dst, const void* tm, int x, int y, unsigned mbar) {
    asm volatile(
        "cp.async.bulk.tensor.3d.shared::cta.global.tile.mbarrier::complete_tx::bytes "
        "[%0], [%1, {%2, %3, %4}], [%5];"
        :: "r"(dst), "l"(tm), "r"(x), "r"(y), "r"(0), "r"(mbar) : "memory");
}
__device__ __forceinline__ void fence_async_shared() {
    asm volatile("fence.proxy.async.shared::cta;" ::: "memory");
}
__device__ __forceinline__ unsigned packh2(float x, float y) {
    __half2 h = __floats2half2_rn(x, y);
    return *(unsigned*)&h;
}

// ---------------------------------------------------------------------------
// fp32 -> fp16 convert
// ---------------------------------------------------------------------------
__global__ void f2h_kernel(const float* __restrict__ in, __half* __restrict__ out, int n4) {
    int i = blockIdx.x * blockDim.x + threadIdx.x;
    if (i < n4) {
        float4 v = ((const float4*)in)[i];
        __half2 h0 = __floats2half2_rn(v.x, v.y);
        __half2 h1 = __floats2half2_rn(v.z, v.w);
        uint2 u;
        u.x = *(unsigned*)&h0;
        u.y = *(unsigned*)&h1;
        ((uint2*)out)[i] = u;
    }
}

// ---------------------------------------------------------------------------
// TMA-fed HMMA GEMM (proven round 8, unchanged).
// ---------------------------------------------------------------------------
#define NSTAGE   3
#define ABYTES   (128 * 64 * 2)
#define STAGEB   (2 * ABYTES)
#define NKCHUNK  16
#define GEMM_DSMEM (NSTAGE * STAGEB + 1024)

template <bool HALF_OUT>
__global__ __launch_bounds__(256, 2)
void gemm_tma_kernel(const __grid_constant__ CUtensorMap tmA,
                     const __grid_constant__ CUtensorMap tmW,
                     const float* __restrict__ bias,
                     void* __restrict__ Cc, int N)
{
    extern __shared__ char dsm_raw[];
    __shared__ __align__(8) unsigned long long s_mbar[NSTAGE];

    char* smb = (char*)(((uintptr_t)dsm_raw + 1023) & ~(uintptr_t)1023);
    const unsigned base = sptr(smb);

    const int tid  = threadIdx.x;
    const int warp = tid >> 5;
    const int lane = tid & 31;
    const int wm   = warp & 3;
    const int wn   = warp >> 2;
    const int g    = lane >> 2;
    const int q    = lane & 3;
    const int la   = lane & 7;
    const int lb   = (lane >> 3) & 1;
    const int lc   = lane >> 4;
    const int bm   = blockIdx.y * 128;
    const int bn   = blockIdx.x * 128;

    unsigned mf[NSTAGE];
#pragma unroll
    for (int s = 0; s < NSTAGE; s++) mf[s] = sptr(&s_mbar[s]);

    if (tid == 0)
#pragma unroll
        for (int s = 0; s < NSTAGE; s++) mbar_init(mf[s], 1);
    __syncthreads();

    if (tid == 0) {
#pragma unroll
        for (int s = 0; s < NSTAGE; s++) {
            mbar_expect(mf[s], STAGEB);
            tma3d(base + s * STAGEB,          &tmA, s * 64, bm, mf[s]);
            tma3d(base + s * STAGEB + ABYTES, &tmW, s * 64, bn, mf[s]);
        }
    }

    float acc[2][8][4];
#pragma unroll
    for (int mt = 0; mt < 2; mt++)
#pragma unroll
        for (int nt = 0; nt < 8; nt++)
#pragma unroll
            for (int c = 0; c < 4; c++) acc[mt][nt][c] = 0.0f;

    for (int c = 0; c < NKCHUNK; c++) {
        const int s = c % NSTAGE;
        const unsigned ph = (unsigned)((c / NSTAGE) & 1);
        mbar_wait(mf[s], ph);

        const unsigned abase = base + s * STAGEB;
        const unsigned bbase = abase + ABYTES;

#pragma unroll
        for (int kk = 0; kk < 4; kk++) {
            unsigned a[2][4];
#pragma unroll
            for (int mt = 0; mt < 2; mt++) {
                int row = wm * 32 + mt * 16 + lb * 8 + la;
                int ch  = (2 * kk + lc) ^ (row & 7);
                ldsm4(a[mt][0], a[mt][1], a[mt][2], a[mt][3],
                      abase + row * 128 + ch * 16);
            }
            unsigned bfr[4][4];
#pragma unroll
            for (int ntp = 0; ntp < 4; ntp++) {
                int row = wn * 64 + ntp * 16 + lc * 8 + la;
                int ch  = (2 * kk + lb) ^ (row & 7);
                ldsm4(bfr[ntp][0], bfr[ntp][1], bfr[ntp][2], bfr[ntp][3],
                      bbase + row * 128 + ch * 16);
            }
#pragma unroll
            for (int mt = 0; mt < 2; mt++)
#pragma unroll
                for (int ntp = 0; ntp < 4; ntp++) {
                    mma16816(acc[mt][2 * ntp],     a[mt][0], a[mt][1], a[mt][2], a[mt][3],
                             bfr[ntp][0], bfr[ntp][1]);
                    mma16816(acc[mt][2 * ntp + 1], a[mt][0], a[mt][1], a[mt][2], a[mt][3],
                             bfr[ntp][2], bfr[ntp][3]);
                }
        }

        __syncthreads();

        if (tid == 0) {
            const int cn = c + NSTAGE;
            if (cn < NKCHUNK) {
                fence_async_shared();
                mbar_expect(mf[s], STAGEB);
                tma3d(abase, &tmA, cn * 64, bm, mf[s]);
                tma3d(bbase, &tmW, cn * 64, bn, mf[s]);
            }
        }
    }

    float2 bv[8];
#pragma unroll
    for (int nt = 0; nt < 8; nt++) {
        int col = bn + wn * 64 + nt * 8 + 2 * q;
        bv[nt].x = bias[col];
        bv[nt].y = bias[col + 1];
    }
#pragma unroll
    for (int mt = 0; mt < 2; mt++) {
        int row = bm + wm * 32 + mt * 16 + g;
#pragma unroll
        for (int nt = 0; nt < 8; nt++) {
            int col = bn + wn * 64 + nt * 8 + 2 * q;
            float x0 = acc[mt][nt][0] + bv[nt].x;
            float y0 = acc[mt][nt][1] + bv[nt].y;
            float x1 = acc[mt][nt][2] + bv[nt].x;
            float y1 = acc[mt][nt][3] + bv[nt].y;
            if (HALF_OUT) {
                __half* O = (__half*)Cc;
                *(__half2*)&O[(size_t)row * N + col]       = __floats2half2_rn(x0, y0);
                *(__half2*)&O[(size_t)(row + 8) * N + col] = __floats2half2_rn(x1, y1);
            } else {
                float* O = (float*)Cc;
                *(float2*)&O[(size_t)row * N + col]       = make_float2(x0, y0);
                *(float2*)&O[(size_t)(row + 8) * N + col] = make_float2(x1, y1);
            }
        }
    }
}

// ---------------------------------------------------------------------------
// Flash attention, FA2-style: BQ=64, BK=64, 4 warps, warp tile = 16 rows x
// FULL 64 cols. Softmax entirely in registers/warp (2 shfls); P stays in
// registers (accumulator layout == A-fragment layout). One syncthreads/iter.
// Double-buffered TMA K/V (SW128, 1024-aligned). smem: K0 K1 V0 V1 | Qs.
// ---------------------------------------------------------------------------
#define FSTR 72
#define FL_TILEB  (64 * 64 * 2)                    // 8 KB
#define FL_QB     (64 * FSTR * 2)                  // 9 KB
#define FL_DSMEM  (4 * FL_TILEB + FL_QB + 1024)

__global__ __launch_bounds__(128, 4)
void flash_f16_kernel(const __grid_constant__ CUtensorMap tmKV,
                      const __half* __restrict__ qkv, __half* __restrict__ out)
{
    extern __shared__ char fraw[];
    __shared__ __align__(8) unsigned long long s_fm[2];

    char* fb = (char*)(((uintptr_t)fraw + 1023) & ~(uintptr_t)1023);
    const unsigned base = sptr(fb);
    const unsigned kbuf[2] = {base,                base + FL_TILEB};
    const unsigned vbuf[2] = {base + 2 * FL_TILEB, base + 3 * FL_TILEB};
    __half* Qs = (__half*)(fb + 4 * FL_TILEB);
    const unsigned qsb = sptr(Qs);
    const unsigned fm[2] = {sptr(&s_fm[0]), sptr(&s_fm[1])};

    const int qt   = (int)gridDim.x - 1 - (int)blockIdx.x;  // heavy tiles first
    const int bh   = blockIdx.y;
    const int bb   = bh >> 4;
    const int h    = bh & 15;
    const int tid  = threadIdx.x;
    const int warp = tid >> 5;     // 0..3, owns rows warp*16..+15
    const int lane = tid & 31;
    const int g    = lane >> 2;
    const int q    = lane & 3;
    const int la   = lane & 7;
    const int lb   = (lane >> 3) & 1;
    const int lc   = lane >> 4;
    const int r0   = warp * 16 + g;
    const int r1   = r0 + 8;

    if (tid == 0) {
        mbar_init(fm[0], 1);
        mbar_init(fm[1], 1);
    }

    // Load Q tile 64x64 (scaled by 1/8, exact in fp16), padded stride 72
    const __half* qb = qkv + (size_t)(bb * T_) * N_QKV + h * D_;
    const __half2 hs = __floats2half2_rn(0.125f, 0.125f);
#pragma unroll
    for (int i = 0; i < 4; i++) {
        int idx = tid + i * 128;           // 0..511 uint4 units
        int r   = idx >> 3;                // 0..63
        int c8  = idx & 7;                 // 0..7
        uint4 v = *(const uint4*)(qb + (size_t)(qt * 64 + r) * N_QKV + 8 * c8);
        __half2* p = (__half2*)&v;
        p[0] = __hmul2(p[0], hs); p[1] = __hmul2(p[1], hs);
        p[2] = __hmul2(p[2], hs); p[3] = __hmul2(p[3], hs);
        *(uint4*)&Qs[r * FSTR + 8 * c8] = v;
    }
    __syncthreads();   // mbar init + Q stores visible

    if (tid == 0) {
        mbar_expect(fm[0], 2 * FL_TILEB);
        tma3d(kbuf[0], &tmKV, C_ + h * 64,     bb * T_ + qt * 64 * 0, fm[0]);
        tma3d(vbuf[0], &tmKV, 2 * C_ + h * 64, bb * T_ + qt * 64 * 0, fm[0]);
    }

    float o[8][4];
#pragma unroll
    for (int j = 0; j < 8; j++)
#pragma unroll
        for (int c = 0; c < 4; c++) o[j][c] = 0.0f;
    float m0 = -1e30f, m1 = -1e30f, l0 = 0.0f, l1 = 0.0f;

    for (int kt = 0; kt <= qt; kt++) {
        const int buf = kt & 1;
        mbar_wait(fm[buf], (unsigned)((kt >> 1) & 1));

        // Prefetch kt+1 into other buffer (its readers finished at the
        // tail syncthreads of iteration kt-1).
        if (tid == 0 && kt < qt) {
            fence_async_shared();
            const int nb = buf ^ 1;
            mbar_expect(fm[nb], 2 * FL_TILEB);
            tma3d(kbuf[nb], &tmKV, C_ + h * 64,     bb * T_ + (kt + 1) * 64, fm[nb]);
            tma3d(vbuf[nb], &tmKV, 2 * C_ + h * 64, bb * T_ + (kt + 1) * 64, fm[nb]);
        }

        // ---- S = Q K^T : warp computes 16 rows x 64 cols (8 n-blocks)
        float s[8][4];
#pragma unroll
        for (int j = 0; j < 8; j++)
#pragma unroll
            for (int c = 0; c < 4; c++) s[j][c] = 0.0f;

#pragma unroll
        for (int kk = 0; kk < 4; kk++) {
            unsigned a0, a1, a2, a3;
            {
                int row = warp * 16 + lb * 8 + la;
                int ch  = 2 * kk + lc;
                ldsm4(a0, a1, a2, a3, qsb + (row * FSTR + ch * 8) * 2);
            }
#pragma unroll
            for (int ntp = 0; ntp < 4; ntp++) {
                unsigned b0, b1, b2, b3;
                int row = ntp * 16 + lc * 8 + la;
                int ch  = (2 * kk + lb) ^ (row & 7);
                ldsm4(b0, b1, b2, b3, kbuf[buf] + row * 128 + ch * 16);
                mma16816(s[2 * ntp],     a0, a1, a2, a3, b0, b1);
                mma16816(s[2 * ntp + 1], a0, a1, a2, a3, b2, b3);
            }
        }

        // Causal mask (diagonal tile only)
        if (kt == qt) {
#pragma unroll
            for (int j = 0; j < 8; j++) {
                int c = j * 8 + 2 * q;
                if (c     > r0) s[j][0] = -1e30f;
                if (c + 1 > r0) s[j][1] = -1e30f;
                if (c     > r1) s[j][2] = -1e30f;
                if (c + 1 > r1) s[j][3] = -1e30f;
            }
        }

        // ---- In-warp online softmax (rows live in lanes q=0..3)
        float mx0 = -1e30f, mx1 = -1e30f;
#pragma unroll
        for (int j = 0; j < 8; j++) {
            mx0 = fmaxf(mx0, fmaxf(s[j][0], s[j][1]));
            mx1 = fmaxf(mx1, fmaxf(s[j][2], s[j][3]));
        }
        mx0 = fmaxf(mx0, __shfl_xor_sync(0xffffffffu, mx0, 1));
        mx0 = fmaxf(mx0, __shfl_xor_sync(0xffffffffu, mx0, 2));
        mx1 = fmaxf(mx1, __shfl_xor_sync(0xffffffffu, mx1, 1));
        mx1 = fmaxf(mx1, __shfl_xor_sync(0xffffffffu, mx1, 2));

        float mn0 = fmaxf(m0, mx0);
        float mn1 = fmaxf(m1, mx1);
        float cr0 = __expf(m0 - mn0);
        float cr1 = __expf(m1 - mn1);
        m0 = mn0; m1 = mn1;

        float sum0 = 0.0f, sum1 = 0.0f;
        unsigned plo[8], phi[8];   // packed P halves: row r0 / row r1
#pragma unroll
        for (int j = 0; j < 8; j++) {
            float p0 = __expf(s[j][0] - mn0);
            float p1 = __expf(s[j][1] - mn0);
            float p2 = __expf(s[j][2] - mn1);
            float p3 = __expf(s[j][3] - mn1);
            sum0 += p0 + p1;
            sum1 += p2 + p3;
            plo[j] = packh2(p0, p1);
            phi[j] = packh2(p2, p3);
        }
        sum0 += __shfl_xor_sync(0xffffffffu, sum0, 1);
        sum0 += __shfl_xor_sync(0xffffffffu, sum0, 2);
        sum1 += __shfl_xor_sync(0xffffffffu, sum1, 1);
        sum1 += __shfl_xor_sync(0xffffffffu, sum1, 2);
        l0 = l0 * cr0 + sum0;
        l1 = l1 * cr1 + sum1;

#pragma unroll
        for (int j = 0; j < 8; j++) {
            o[j][0] *= cr0; o[j][1] *= cr0;
            o[j][2] *= cr1; o[j][3] *= cr1;
        }

        // ---- O += P V : P directly from registers (acc layout == A layout)
#pragma unroll
        for (int t = 0; t < 4; t++) {
            const unsigned a0 = plo[2 * t];
            const unsigned a1 = phi[2 * t];
            const unsigned a2 = plo[2 * t + 1];
            const unsigned a3 = phi[2 * t + 1];
#pragma unroll
            for (int ntp = 0; ntp < 4; ntp++) {
                unsigned b0, b1, b2, b3;
                int row = t * 16 + lb * 8 + la;
                int ch  = (2 * ntp + lc) ^ (row & 7);
                ldsm4t(b0, b1, b2, b3, vbuf[buf] + row * 128 + ch * 16);
                mma16816(o[2 * ntp],     a0, a1, a2, a3, b0, b1);
                mma16816(o[2 * ntp + 1], a0, a1, a2, a3, b2, b3);
            }
        }

        __syncthreads();   // all warps done reading buf before it is refilled
    }

    // Epilogue
    float il0 = 1.0f / l0;
    float il1 = 1.0f / l1;
    size_t row0 = (size_t)(bb * T_ + qt * 64 + r0);
    size_t row1 = (size_t)(bb * T_ + qt * 64 + r1);
#pragma unroll
    for (int j = 0; j < 8; j++) {
        int col = h * 64 + j * 8 + 2 * q;
        *(__half2*)&out[row0 * C_ + col] = __floats2half2_rn(o[j][0] * il0, o[j][1] * il0);
        *(__half2*)&out[row1 * C_ + col] = __floats2half2_rn(o[j][2] * il1, o[j][3] * il1);
    }
}

// ---------------------------------------------------------------------------
// Host: tensormaps + launch
// ---------------------------------------------------------------------------
typedef CUresult (*PFN_encode)(CUtensorMap*, CUtensorMapDataType, cuuint32_t, void*,
                               const cuuint64_t*, const cuuint64_t*, const cuuint32_t*,
                               const cuuint32_t*, CUtensorMapInterleave, CUtensorMapSwizzle,
                               CUtensorMapL2promotion, CUtensorMapFloatOOBfill);

static void make_map(PFN_encode enc, CUtensorMap* tm, void* ptr,
                     unsigned long long cols, unsigned long long rows,
                     unsigned bx, unsigned by) {
    cuuint64_t dims[3]    = {cols, rows, 1};
    cuuint64_t strides[2] = {cols * 2, rows * cols * 2};
    cuuint32_t box[3]     = {bx, by, 1};
    cuuint32_t es[3]      = {1, 1, 1};
    enc(tm, CU_TENSOR_MAP_DATA_TYPE_FLOAT16, 3, ptr, dims, strides, box, es,
        CU_TENSOR_MAP_INTERLEAVE_NONE, CU_TENSOR_MAP_SWIZZLE_128B,
        CU_TENSOR_MAP_L2_PROMOTION_L2_128B, CU_TENSOR_MAP_FLOAT_OOB_FILL_NONE);
}

extern "C" void kernel_launch(void* const* d_in, const int* in_sizes, int n_in,
                              void* d_out, int out_size)
{
    const float* x      = (const float*)d_in[0];
    const float* W_qkv  = (const float*)d_in[1];
    const float* b_qkv  = (const float*)d_in[2];
    const float* W_proj = (const float*)d_in[3];
    const float* b_proj = (const float*)d_in[4];
    float* out = (float*)d_out;

    __half *hx, *hw1, *hw2, *qkv, *att;
    cudaGetSymbolAddress((void**)&hx,  g_hx);
    cudaGetSymbolAddress((void**)&hw1, g_hw1);
    cudaGetSymbolAddress((void**)&hw2, g_hw2);
    cudaGetSymbolAddress((void**)&qkv, g_qkv);
    cudaGetSymbolAddress((void**)&att, g_att);

    void* fnp = nullptr;
    cudaDriverEntryPointQueryResult qr;
    cudaGetDriverEntryPointByVersion("cuTensorMapEncodeTiled", &fnp, 12000,
                                     cudaEnableDefault, &qr);
    PFN_encode enc = (PFN_encode)fnp;

    CUtensorMap tmX, tmW1, tmAtt, tmW2, tmKV;
    make_map(enc, &tmX,   hx,  C_,    M_,    64, 128);
    make_map(enc, &tmW1,  hw1, C_,    N_QKV, 64, 128);
    make_map(enc, &tmAtt, att, C_,    M_,    64, 128);
    make_map(enc, &tmW2,  hw2, C_,    C_,    64, 128);
    make_map(enc, &tmKV,  qkv, N_QKV, M_,    64, 64);

    // 0) fp32 -> fp16 converts
    f2h_kernel<<<(M_ * C_ / 4 + 255) / 256, 256>>>(x, hx, M_ * C_ / 4);
    f2h_kernel<<<(N_QKV * C_ / 4 + 255) / 256, 256>>>(W_qkv, hw1, N_QKV * C_ / 4);
    f2h_kernel<<<(C_ * C_ / 4 + 255) / 256, 256>>>(W_proj, hw2, C_ * C_ / 4);

    // 1) qkv = x @ W_qkv^T + b_qkv (half out)
    cudaFuncSetAttribute((const void*)gemm_tma_kernel<true>,
                         cudaFuncAttributeMaxDynamicSharedMemorySize, GEMM_DSMEM);
    gemm_tma_kernel<true><<<dim3(N_QKV / 128, M_ / 128), 256, GEMM_DSMEM>>>(
        tmX, tmW1, b_qkv, qkv, N_QKV);

    // 2) flash attention (FA2 register pipeline, 128 threads, TMA K/V)
    cudaFuncSetAttribute(flash_f16_kernel,
                         cudaFuncAttributeMaxDynamicSharedMemorySize, FL_DSMEM);
    flash_f16_kernel<<<dim3(T_ / 64, B_ * H_), 128, FL_DSMEM>>>(tmKV, qkv, att);

    // 3) out = att @ W_proj^T + b_proj (float out)
    cudaFuncSetAttribute((const void*)gemm_tma_kernel<false>,
                         cudaFuncAttributeMaxDynamicSharedMemorySize, GEMM_DSMEM);
    gemm_tma_kernel<false><<<dim3(C_ / 128, M_ / 128), 256, GEMM_DSMEM>>>(
        tmAtt, tmW2, b_proj, out, C_);
}

// round 11
// speedup vs baseline: 1.3762x; 1.0806x over previous
#include <cuda_runtime.h>
#include <cuda.h>
#include <cuda_fp16.h>
#include <math.h>
#include <stdint.h>

// ---------------------------------------------------------------------------
// Problem constants
// ---------------------------------------------------------------------------
#define B_    4
#define T_    2048
#define C_    1024
#define H_    16
#define D_    64
#define M_    (B_ * T_)        // 8192
#define N_QKV (3 * C_)         // 3072

// Scratch (__device__ globals; allocation-free rule)
__device__ __half g_hx[M_ * C_];
__device__ __half g_hw1[N_QKV * C_];
__device__ __half g_hw2[C_ * C_];
__device__ __half g_qkv[(size_t)M_ * N_QKV];
__device__ __half g_att[M_ * C_];

// ---------------------------------------------------------------------------
// PTX helpers
// ---------------------------------------------------------------------------
__device__ __forceinline__ unsigned sptr(const void* p) {
    return (unsigned)__cvta_generic_to_shared(p);
}
__device__ __forceinline__ void ldsm4(unsigned& r0, unsigned& r1,
                                      unsigned& r2, unsigned& r3, unsigned a) {
    asm volatile("ldmatrix.sync.aligned.m8n8.x4.shared.b16 {%0,%1,%2,%3},[%4];"
                 : "=r"(r0), "=r"(r1), "=r"(r2), "=r"(r3) : "r"(a));
}
__device__ __forceinline__ void ldsm4t(unsigned& r0, unsigned& r1,
                                       unsigned& r2, unsigned& r3, unsigned a) {
    asm volatile("ldmatrix.sync.aligned.m8n8.x4.trans.shared.b16 {%0,%1,%2,%3},[%4];"
                 : "=r"(r0), "=r"(r1), "=r"(r2), "=r"(r3) : "r"(a));
}
__device__ __forceinline__ void mma16816(float* d,
                                         unsigned a0, unsigned a1, unsigned a2, unsigned a3,
                                         unsigned b0, unsigned b1) {
    asm volatile(
        "mma.sync.aligned.m16n8k16.row.col.f32.f16.f16.f32 "
        "{%0,%1,%2,%3},{%4,%5,%6,%7},{%8,%9},{%0,%1,%2,%3};"
        : "+f"(d[0]), "+f"(d[1]), "+f"(d[2]), "+f"(d[3])
        : "r"(a0), "r"(a1), "r"(a2), "r"(a3), "r"(b0), "r"(b1));
}
__device__ __forceinline__ void mbar_init(unsigned a, unsigned cnt) {
    asm volatile("mbarrier.init.shared.b64 [%0], %1;" :: "r"(a), "r"(cnt) : "memory");
}
__device__ __forceinline__ void mbar_expect(unsigned a, unsigned bytes) {
    asm volatile("mbarrier.arrive.expect_tx.shared.b64 _, [%0], %1;"
                 :: "r"(a), "r"(bytes) : "memory");
}
__device__ __forceinline__ void mbar_arrive(unsigned a) {
    asm volatile("mbarrier.arrive.shared.b64 _, [%0];" :: "r"(a) : "memory");
}
__device__ __forceinline__ void mbar_wait(unsigned a, unsigned parity) {
    asm volatile(
        "{\n\t.reg .pred P;\n\t"
        "W%=:\n\t"
        "mbarrier.try_wait.parity.acquire.cta.shared::cta.b64 P, [%0], %1, 0x989680;\n\t"
        "@P bra.uni D%=;\n\t"
        "bra.uni W%=;\n\t"
        "D%=:\n\t}"
        :: "r"(a), "r"(parity) : "memory");
}
__device__ __forceinline__ void tma3d(unsigned dst, const void* tm, int x, int y, unsigned mbar) {
    asm volatile(
        "cp.async.bulk.tensor.3d.shared::cta.global.tile.mbarrier::complete_tx::bytes "
        "[%0], [%1, {%2, %3, %4}], [%5];"
        :: "r"(dst), "l"(tm), "r"(x), "r"(y), "r"(0), "r"(mbar) : "memory");
}
__device__ __forceinline__ void fence_async_shared() {
    asm volatile("fence.proxy.async.shared::cta;" ::: "memory");
}
__device__ __forceinline__ unsigned packh2(float x, float y) {
    __half2 h = __floats2half2_rn(x, y);
    return *(unsigned*)&h;
}

// ---------------------------------------------------------------------------
// fp32 -> fp16 convert
// ---------------------------------------------------------------------------
__global__ void f2h_kernel(const float* __restrict__ in, __half* __restrict__ out, int n4) {
    int i = blockIdx.x * blockDim.x + threadIdx.x;
    if (i < n4) {
        float4 v = ((const float4*)in)[i];
        __half2 h0 = __floats2half2_rn(v.x, v.y);
        __half2 h1 = __floats2half2_rn(v.z, v.w);
        uint2 u;
        u.x = *(unsigned*)&h0;
        u.y = *(unsigned*)&h1;
        ((uint2*)out)[i] = u;
    }
}

// ---------------------------------------------------------------------------
// TMA-fed HMMA GEMM, free-running warps: per-stage empty mbarriers (count 8)
// replace the per-chunk __syncthreads. Warps skew up to ring depth.
// ---------------------------------------------------------------------------
#define NSTAGE   3
#define ABYTES   (128 * 64 * 2)
#define STAGEB   (2 * ABYTES)
#define NKCHUNK  16
#define GEMM_DSMEM (NSTAGE * STAGEB + 1024)

template <bool HALF_OUT>
__global__ __launch_bounds__(256, 2)
void gemm_tma_kernel(const __grid_constant__ CUtensorMap tmA,
                     const __grid_constant__ CUtensorMap tmW,
                     const float* __restrict__ bias,
                     void* __restrict__ Cc, int N)
{
    extern __shared__ char dsm_raw[];
    __shared__ __align__(8) unsigned long long s_mbar[2 * NSTAGE];

    char* smb = (char*)(((uintptr_t)dsm_raw + 1023) & ~(uintptr_t)1023);
    const unsigned base = sptr(smb);

    const int tid  = threadIdx.x;
    const int warp = tid >> 5;
    const int lane = tid & 31;
    const int wm   = warp & 3;
    const int wn   = warp >> 2;
    const int g    = lane >> 2;
    const int q    = lane & 3;
    const int la   = lane & 7;
    const int lb   = (lane >> 3) & 1;
    const int lc   = lane >> 4;
    const int bm   = blockIdx.y * 128;
    const int bn   = blockIdx.x * 128;

    unsigned mf[NSTAGE], me[NSTAGE];
#pragma unroll
    for (int s = 0; s < NSTAGE; s++) {
        mf[s] = sptr(&s_mbar[s]);
        me[s] = sptr(&s_mbar[NSTAGE + s]);
    }

    if (tid == 0) {
#pragma unroll
        for (int s = 0; s < NSTAGE; s++) {
            mbar_init(mf[s], 1);
            mbar_init(me[s], 8);
        }
    }
    __syncthreads();

    if (tid == 0) {
#pragma unroll
        for (int s = 0; s < NSTAGE; s++) {
            mbar_expect(mf[s], STAGEB);
            tma3d(base + s * STAGEB,          &tmA, s * 64, bm, mf[s]);
            tma3d(base + s * STAGEB + ABYTES, &tmW, s * 64, bn, mf[s]);
        }
    }

    float acc[2][8][4];
#pragma unroll
    for (int mt = 0; mt < 2; mt++)
#pragma unroll
        for (int nt = 0; nt < 8; nt++)
#pragma unroll
            for (int c = 0; c < 4; c++) acc[mt][nt][c] = 0.0f;

    for (int c = 0; c < NKCHUNK; c++) {
        const int s = c % NSTAGE;
        const unsigned ph = (unsigned)((c / NSTAGE) & 1);
        mbar_wait(mf[s], ph);

        const unsigned abase = base + s * STAGEB;
        const unsigned bbase = abase + ABYTES;

#pragma unroll
        for (int kk = 0; kk < 4; kk++) {
            unsigned a[2][4];
#pragma unroll
            for (int mt = 0; mt < 2; mt++) {
                int row = wm * 32 + mt * 16 + lb * 8 + la;
                int ch  = (2 * kk + lc) ^ (row & 7);
                ldsm4(a[mt][0], a[mt][1], a[mt][2], a[mt][3],
                      abase + row * 128 + ch * 16);
            }
            unsigned bfr[4][4];
#pragma unroll
            for (int ntp = 0; ntp < 4; ntp++) {
                int row = wn * 64 + ntp * 16 + lc * 8 + la;
                int ch  = (2 * kk + lb) ^ (row & 7);
                ldsm4(bfr[ntp][0], bfr[ntp][1], bfr[ntp][2], bfr[ntp][3],
                      bbase + row * 128 + ch * 16);
            }
#pragma unroll
            for (int mt = 0; mt < 2; mt++)
#pragma unroll
                for (int ntp = 0; ntp < 4; ntp++) {
                    mma16816(acc[mt][2 * ntp],     a[mt][0], a[mt][1], a[mt][2], a[mt][3],
                             bfr[ntp][0], bfr[ntp][1]);
                    mma16816(acc[mt][2 * ntp + 1], a[mt][0], a[mt][1], a[mt][2], a[mt][3],
                             bfr[ntp][2], bfr[ntp][3]);
                }
        }

        // This warp is done reading stage s (ldmatrix is warp-synchronous).
        if (lane == 0) mbar_arrive(me[s]);

        // Producer: re-arm stage s for chunk c+NSTAGE once all 8 warps arrived.
        if (tid == 0) {
            const int cn = c + NSTAGE;
            if (cn < NKCHUNK) {
                mbar_wait(me[s], ph);     // empty completion #(c/NSTAGE)
                fence_async_shared();
                mbar_expect(mf[s], STAGEB);
                tma3d(abase, &tmA, cn * 64, bm, mf[s]);
                tma3d(bbase, &tmW, cn * 64, bn, mf[s]);
            }
        }
    }

    float2 bv[8];
#pragma unroll
    for (int nt = 0; nt < 8; nt++) {
        int col = bn + wn * 64 + nt * 8 + 2 * q;
        bv[nt].x = bias[col];
        bv[nt].y = bias[col + 1];
    }
#pragma unroll
    for (int mt = 0; mt < 2; mt++) {
        int row = bm + wm * 32 + mt * 16 + g;
#pragma unroll
        for (int nt = 0; nt < 8; nt++) {
            int col = bn + wn * 64 + nt * 8 + 2 * q;
            float x0 = acc[mt][nt][0] + bv[nt].x;
            float y0 = acc[mt][nt][1] + bv[nt].y;
            float x1 = acc[mt][nt][2] + bv[nt].x;
            float y1 = acc[mt][nt][3] + bv[nt].y;
            if (HALF_OUT) {
                __half* O = (__half*)Cc;
                *(__half2*)&O[(size_t)row * N + col]       = __floats2half2_rn(x0, y0);
                *(__half2*)&O[(size_t)(row + 8) * N + col] = __floats2half2_rn(x1, y1);
            } else {
                float* O = (float*)Cc;
                *(float2*)&O[(size_t)row * N + col]       = make_float2(x0, y0);
                *(float2*)&O[(size_t)(row + 8) * N + col] = make_float2(x1, y1);
            }
        }
    }
}

// ---------------------------------------------------------------------------
// Flash attention (FA2 register pipeline, round 10) with the per-iteration
// __syncthreads replaced by per-buffer empty mbarriers (count 4).
// ---------------------------------------------------------------------------
#define FSTR 72
#define FL_TILEB  (64 * 64 * 2)                    // 8 KB
#define FL_QB     (64 * FSTR * 2)                  // 9 KB
#define FL_DSMEM  (4 * FL_TILEB + FL_QB + 1024)

__global__ __launch_bounds__(128, 4)
void flash_f16_kernel(const __grid_constant__ CUtensorMap tmKV,
                      const __half* __restrict__ qkv, __half* __restrict__ out)
{
    extern __shared__ char fraw[];
    __shared__ __align__(8) unsigned long long s_fm[2];
    __shared__ __align__(8) unsigned long long s_fe[2];

    char* fb = (char*)(((uintptr_t)fraw + 1023) & ~(uintptr_t)1023);
    const unsigned base = sptr(fb);
    const unsigned kbuf[2] = {base,                base + FL_TILEB};
    const unsigned vbuf[2] = {base + 2 * FL_TILEB, base + 3 * FL_TILEB};
    __half* Qs = (__half*)(fb + 4 * FL_TILEB);
    const unsigned qsb = sptr(Qs);
    const unsigned fm[2] = {sptr(&s_fm[0]), sptr(&s_fm[1])};
    const unsigned fe[2] = {sptr(&s_fe[0]), sptr(&s_fe[1])};

    const int qt   = (int)gridDim.x - 1 - (int)blockIdx.x;  // heavy tiles first
    const int bh   = blockIdx.y;
    const int bb   = bh >> 4;
    const int h    = bh & 15;
    const int tid  = threadIdx.x;
    const int warp = tid >> 5;     // 0..3, owns rows warp*16..+15
    const int lane = tid & 31;
    const int g    = lane >> 2;
    const int q    = lane & 3;
    const int la   = lane & 7;
    const int lb   = (lane >> 3) & 1;
    const int lc   = lane >> 4;
    const int r0   = warp * 16 + g;
    const int r1   = r0 + 8;

    if (tid == 0) {
        mbar_init(fm[0], 1);
        mbar_init(fm[1], 1);
        mbar_init(fe[0], 4);
        mbar_init(fe[1], 4);
    }

    // Load Q tile 64x64 (scaled by 1/8, exact in fp16), padded stride 72
    const __half* qb = qkv + (size_t)(bb * T_) * N_QKV + h * D_;
    const __half2 hs = __floats2half2_rn(0.125f, 0.125f);
#pragma unroll
    for (int i = 0; i < 4; i++) {
        int idx = tid + i * 128;
        int r   = idx >> 3;
        int c8  = idx & 7;
        uint4 v = *(const uint4*)(qb + (size_t)(qt * 64 + r) * N_QKV + 8 * c8);
        __half2* p = (__half2*)&v;
        p[0] = __hmul2(p[0], hs); p[1] = __hmul2(p[1], hs);
        p[2] = __hmul2(p[2], hs); p[3] = __hmul2(p[3], hs);
        *(uint4*)&Qs[r * FSTR + 8 * c8] = v;
    }
    __syncthreads();   // mbar init + Q stores visible to all warps

    if (tid == 0) {
        mbar_expect(fm[0], 2 * FL_TILEB);
        tma3d(kbuf[0], &tmKV, C_ + h * 64,     bb * T_, fm[0]);
        tma3d(vbuf[0], &tmKV, 2 * C_ + h * 64, bb * T_, fm[0]);
    }

    float o[8][4];
#pragma unroll
    for (int j = 0; j < 8; j++)
#pragma unroll
        for (int c = 0; c < 4; c++) o[j][c] = 0.0f;
    float m0 = -1e30f, m1 = -1e30f, l0 = 0.0f, l1 = 0.0f;

    for (int kt = 0; kt <= qt; kt++) {
        const int buf = kt & 1;
        mbar_wait(fm[buf], (unsigned)((kt >> 1) & 1));

        // Producer: prefetch kt+1 into the other buffer once its last
        // readers (iteration kt-1) have arrived on fe[nb].
        if (tid == 0 && kt < qt) {
            const int nb = buf ^ 1;
            if (kt > 0) mbar_wait(fe[nb], (unsigned)(((kt - 1) >> 1) & 1));
            fence_async_shared();
            mbar_expect(fm[nb], 2 * FL_TILEB);
            tma3d(kbuf[nb], &tmKV, C_ + h * 64,     bb * T_ + (kt + 1) * 64, fm[nb]);
            tma3d(vbuf[nb], &tmKV, 2 * C_ + h * 64, bb * T_ + (kt + 1) * 64, fm[nb]);
        }

        // ---- S = Q K^T : warp computes 16 rows x 64 cols
        float s[8][4];
#pragma unroll
        for (int j = 0; j < 8; j++)
#pragma unroll
            for (int c = 0; c < 4; c++) s[j][c] = 0.0f;

#pragma unroll
        for (int kk = 0; kk < 4; kk++) {
            unsigned a0, a1, a2, a3;
            {
                int row = warp * 16 + lb * 8 + la;
                int ch  = 2 * kk + lc;
                ldsm4(a0, a1, a2, a3, qsb + (row * FSTR + ch * 8) * 2);
            }
#pragma unroll
            for (int ntp = 0; ntp < 4; ntp++) {
                unsigned b0, b1, b2, b3;
                int row = ntp * 16 + lc * 8 + la;
                int ch  = (2 * kk + lb) ^ (row & 7);
                ldsm4(b0, b1, b2, b3, kbuf[buf] + row * 128 + ch * 16);
                mma16816(s[2 * ntp],     a0, a1, a2, a3, b0, b1);
                mma16816(s[2 * ntp + 1], a0, a1, a2, a3, b2, b3);
            }
        }

        // Causal mask (diagonal tile only)
        if (kt == qt) {
#pragma unroll
            for (int j = 0; j < 8; j++) {
                int c = j * 8 + 2 * q;
                if (c     > r0) s[j][0] = -1e30f;
                if (c + 1 > r0) s[j][1] = -1e30f;
                if (c     > r1) s[j][2] = -1e30f;
                if (c + 1 > r1) s[j][3] = -1e30f;
            }
        }

        // ---- In-warp online softmax
        float mx0 = -1e30f, mx1 = -1e30f;
#pragma unroll
        for (int j = 0; j < 8; j++) {
            mx0 = fmaxf(mx0, fmaxf(s[j][0], s[j][1]));
            mx1 = fmaxf(mx1, fmaxf(s[j][2], s[j][3]));
        }
        mx0 = fmaxf(mx0, __shfl_xor_sync(0xffffffffu, mx0, 1));
        mx0 = fmaxf(mx0, __shfl_xor_sync(0xffffffffu, mx0, 2));
        mx1 = fmaxf(mx1, __shfl_xor_sync(0xffffffffu, mx1, 1));
        mx1 = fmaxf(mx1, __shfl_xor_sync(0xffffffffu, mx1, 2));

        float mn0 = fmaxf(m0, mx0);
        float mn1 = fmaxf(m1, mx1);
        float cr0 = __expf(m0 - mn0);
        float cr1 = __expf(m1 - mn1);
        m0 = mn0; m1 = mn1;

        float sum0 = 0.0f, sum1 = 0.0f;
        unsigned plo[8], phi[8];
#pragma unroll
        for (int j = 0; j < 8; j++) {
            float p0 = __expf(s[j][0] - mn0);
            float p1 = __expf(s[j][1] - mn0);
            float p2 = __expf(s[j][2] - mn1);
            float p3 = __expf(s[j][3] - mn1);
            sum0 += p0 + p1;
            sum1 += p2 + p3;
            plo[j] = packh2(p0, p1);
            phi[j] = packh2(p2, p3);
        }
        sum0 += __shfl_xor_sync(0xffffffffu, sum0, 1);
        sum0 += __shfl_xor_sync(0xffffffffu, sum0, 2);
        sum1 += __shfl_xor_sync(0xffffffffu, sum1, 1);
        sum1 += __shfl_xor_sync(0xffffffffu, sum1, 2);
        l0 = l0 * cr0 + sum0;
        l1 = l1 * cr1 + sum1;

#pragma unroll
        for (int j = 0; j < 8; j++) {
            o[j][0] *= cr0; o[j][1] *= cr0;
            o[j][2] *= cr1; o[j][3] *= cr1;
        }

        // ---- O += P V : P directly from registers
#pragma unroll
        for (int t = 0; t < 4; t++) {
            const unsigned a0 = plo[2 * t];
            const unsigned a1 = phi[2 * t];
            const unsigned a2 = plo[2 * t + 1];
            const unsigned a3 = phi[2 * t + 1];
#pragma unroll
            for (int ntp = 0; ntp < 4; ntp++) {
                unsigned b0, b1, b2, b3;
                int row = t * 16 + lb * 8 + la;
                int ch  = (2 * ntp + lc) ^ (row & 7);
                ldsm4t(b0, b1, b2, b3, vbuf[buf] + row * 128 + ch * 16);
                mma16816(o[2 * ntp],     a0, a1, a2, a3, b0, b1);
                mma16816(o[2 * ntp + 1], a0, a1, a2, a3, b2, b3);
            }
        }

        // This warp is done reading K/V of buf.
        if (lane == 0) mbar_arrive(fe[buf]);
    }

    // Epilogue
    float il0 = 1.0f / l0;
    float il1 = 1.0f / l1;
    size_t row0 = (size_t)(bb * T_ + qt * 64 + r0);
    size_t row1 = (size_t)(bb * T_ + qt * 64 + r1);
#pragma unroll
    for (int j = 0; j < 8; j++) {
        int col = h * 64 + j * 8 + 2 * q;
        *(__half2*)&out[row0 * C_ + col] = __floats2half2_rn(o[j][0] * il0, o[j][1] * il0);
        *(__half2*)&out[row1 * C_ + col] = __floats2half2_rn(o[j][2] * il1, o[j][3] * il1);
    }
}

// ---------------------------------------------------------------------------
// Host: tensormaps + launch
// ---------------------------------------------------------------------------
typedef CUresult (*PFN_encode)(CUtensorMap*, CUtensorMapDataType, cuuint32_t, void*,
                               const cuuint64_t*, const cuuint64_t*, const cuuint32_t*,
                               const cuuint32_t*, CUtensorMapInterleave, CUtensorMapSwizzle,
                               CUtensorMapL2promotion, CUtensorMapFloatOOBfill);

static void make_map(PFN_encode enc, CUtensorMap* tm, void* ptr,
                     unsigned long long cols, unsigned long long rows,
                     unsigned bx, unsigned by) {
    cuuint64_t dims[3]    = {cols, rows, 1};
    cuuint64_t strides[2] = {cols * 2, rows * cols * 2};
    cuuint32_t box[3]     = {bx, by, 1};
    cuuint32_t es[3]      = {1, 1, 1};
    enc(tm, CU_TENSOR_MAP_DATA_TYPE_FLOAT16, 3, ptr, dims, strides, box, es,
        CU_TENSOR_MAP_INTERLEAVE_NONE, CU_TENSOR_MAP_SWIZZLE_128B,
        CU_TENSOR_MAP_L2_PROMOTION_L2_128B, CU_TENSOR_MAP_FLOAT_OOB_FILL_NONE);
}

extern "C" void kernel_launch(void* const* d_in, const int* in_sizes, int n_in,
                              void* d_out, int out_size)
{
    const float* x      = (const float*)d_in[0];
    const float* W_qkv  = (const float*)d_in[1];
    const float* b_qkv  = (const float*)d_in[2];
    const float* W_proj = (const float*)d_in[3];
    const float* b_proj = (const float*)d_in[4];
    float* out = (float*)d_out;

    __half *hx, *hw1, *hw2, *qkv, *att;
    cudaGetSymbolAddress((void**)&hx,  g_hx);
    cudaGetSymbolAddress((void**)&hw1, g_hw1);
    cudaGetSymbolAddress((void**)&hw2, g_hw2);
    cudaGetSymbolAddress((void**)&qkv, g_qkv);
    cudaGetSymbolAddress((void**)&att, g_att);

    void* fnp = nullptr;
    cudaDriverEntryPointQueryResult qr;
    cudaGetDriverEntryPointByVersion("cuTensorMapEncodeTiled", &fnp, 12000,
                                     cudaEnableDefault, &qr);
    PFN_encode enc = (PFN_encode)fnp;

    CUtensorMap tmX, tmW1, tmAtt, tmW2, tmKV;
    make_map(enc, &tmX,   hx,  C_,    M_,    64, 128);
    make_map(enc, &tmW1,  hw1, C_,    N_QKV, 64, 128);
    make_map(enc, &tmAtt, att, C_,    M_,    64, 128);
    make_map(enc, &tmW2,  hw2, C_,    C_,    64, 128);
    make_map(enc, &tmKV,  qkv, N_QKV, M_,    64, 64);

    // 0) fp32 -> fp16 converts
    f2h_kernel<<<(M_ * C_ / 4 + 255) / 256, 256>>>(x, hx, M_ * C_ / 4);
    f2h_kernel<<<(N_QKV * C_ / 4 + 255) / 256, 256>>>(W_qkv, hw1, N_QKV * C_ / 4);
    f2h_kernel<<<(C_ * C_ / 4 + 255) / 256, 256>>>(W_proj, hw2, C_ * C_ / 4);

    // 1) qkv = x @ W_qkv^T + b_qkv (half out)
    cudaFuncSetAttribute((const void*)gemm_tma_kernel<true>,
                         cudaFuncAttributeMaxDynamicSharedMemorySize, GEMM_DSMEM);
    gemm_tma_kernel<true><<<dim3(N_QKV / 128, M_ / 128), 256, GEMM_DSMEM>>>(
        tmX, tmW1, b_qkv, qkv, N_QKV);

    // 2) flash attention (free-running warps, TMA K/V)
    cudaFuncSetAttribute(flash_f16_kernel,
                         cudaFuncAttributeMaxDynamicSharedMemorySize, FL_DSMEM);
    flash_f16_kernel<<<dim3(T_ / 64, B_ * H_), 128, FL_DSMEM>>>(tmKV, qkv, att);

    // 3) out = att @ W_proj^T + b_proj (float out)
    cudaFuncSetAttribute((const void*)gemm_tma_kernel<false>,
                         cudaFuncAttributeMaxDynamicSharedMemorySize, GEMM_DSMEM);
    gemm_tma_kernel<false><<<dim3(C_ / 128, M_ / 128), 256, GEMM_DSMEM>>>(
        tmAtt, tmW2, b_proj, out, C_);
}

// round 12
// speedup vs baseline: 1.4043x; 1.0204x over previous
#include <cuda_runtime.h>
#include <cuda.h>
#include <cuda_fp16.h>
#include <math.h>
#include <stdint.h>

// ---------------------------------------------------------------------------
// Problem constants
// ---------------------------------------------------------------------------
#define B_    4
#define T_    2048
#define C_    1024
#define H_    16
#define D_    64
#define M_    (B_ * T_)        // 8192
#define N_QKV (3 * C_)         // 3072

// Scratch (__device__ globals; allocation-free rule)
__device__ __half g_hx[M_ * C_];
__device__ __half g_hw1[N_QKV * C_];
__device__ __half g_hw2[C_ * C_];
__device__ __half g_qkv[(size_t)M_ * N_QKV];
__device__ __half g_att[M_ * C_];

// ---------------------------------------------------------------------------
// PTX helpers
// ---------------------------------------------------------------------------
__device__ __forceinline__ unsigned sptr(const void* p) {
    return (unsigned)__cvta_generic_to_shared(p);
}
__device__ __forceinline__ void ldsm4(unsigned& r0, unsigned& r1,
                                      unsigned& r2, unsigned& r3, unsigned a) {
    asm volatile("ldmatrix.sync.aligned.m8n8.x4.shared.b16 {%0,%1,%2,%3},[%4];"
                 : "=r"(r0), "=r"(r1), "=r"(r2), "=r"(r3) : "r"(a));
}
__device__ __forceinline__ void ldsm4t(unsigned& r0, unsigned& r1,
                                       unsigned& r2, unsigned& r3, unsigned a) {
    asm volatile("ldmatrix.sync.aligned.m8n8.x4.trans.shared.b16 {%0,%1,%2,%3},[%4];"
                 : "=r"(r0), "=r"(r1), "=r"(r2), "=r"(r3) : "r"(a));
}
__device__ __forceinline__ void mma16816(float* d,
                                         unsigned a0, unsigned a1, unsigned a2, unsigned a3,
                                         unsigned b0, unsigned b1) {
    asm volatile(
        "mma.sync.aligned.m16n8k16.row.col.f32.f16.f16.f32 "
        "{%0,%1,%2,%3},{%4,%5,%6,%7},{%8,%9},{%0,%1,%2,%3};"
        : "+f"(d[0]), "+f"(d[1]), "+f"(d[2]), "+f"(d[3])
        : "r"(a0), "r"(a1), "r"(a2), "r"(a3), "r"(b0), "r"(b1));
}
__device__ __forceinline__ void mbar_init(unsigned a, unsigned cnt) {
    asm volatile("mbarrier.init.shared.b64 [%0], %1;" :: "r"(a), "r"(cnt) : "memory");
}
__device__ __forceinline__ void mbar_expect(unsigned a, unsigned bytes) {
    asm volatile("mbarrier.arrive.expect_tx.shared.b64 _, [%0], %1;"
                 :: "r"(a), "r"(bytes) : "memory");
}
__device__ __forceinline__ void mbar_arrive(unsigned a) {
    asm volatile("mbarrier.arrive.shared.b64 _, [%0];" :: "r"(a) : "memory");
}
__device__ __forceinline__ void mbar_wait(unsigned a, unsigned parity) {
    asm volatile(
        "{\n\t.reg .pred P;\n\t"
        "W%=:\n\t"
        "mbarrier.try_wait.parity.acquire.cta.shared::cta.b64 P, [%0], %1, 0x989680;\n\t"
        "@P bra.uni D%=;\n\t"
        "bra.uni W%=;\n\t"
        "D%=:\n\t}"
        :: "r"(a), "r"(parity) : "memory");
}
__device__ __forceinline__ void tma3d(unsigned dst, const void* tm, int x, int y, unsigned mbar) {
    asm volatile(
        "cp.async.bulk.tensor.3d.shared::cta.global.tile.mbarrier::complete_tx::bytes "
        "[%0], [%1, {%2, %3, %4}], [%5];"
        :: "r"(dst), "l"(tm), "r"(x), "r"(y), "r"(0), "r"(mbar) : "memory");
}
__device__ __forceinline__ void fence_async_shared() {
    asm volatile("fence.proxy.async.shared::cta;" ::: "memory");
}
__device__ __forceinline__ unsigned packh2(float x, float y) {
    __half2 h = __floats2half2_rn(x, y);
    return *(unsigned*)&h;
}

// ---------------------------------------------------------------------------
// Fused fp32 -> fp16 convert for x, W_qkv, W_proj (one launch)
// ---------------------------------------------------------------------------
#define XN4  (M_ * C_ / 4)
#define W1N4 (N_QKV * C_ / 4)
#define W2N4 (C_ * C_ / 4)
#define CVT_TOTAL (XN4 + W1N4 + W2N4)

__global__ void f2h_all_kernel(const float* __restrict__ x,
                               const float* __restrict__ w1,
                               const float* __restrict__ w2,
                               __half* __restrict__ hx,
                               __half* __restrict__ hw1,
                               __half* __restrict__ hw2) {
    int i = blockIdx.x * blockDim.x + threadIdx.x;
    if (i >= CVT_TOTAL) return;
    const float* src;
    __half* dst;
    int j = i;
    if (j < XN4) { src = x; dst = hx; }
    else if ((j -= XN4) < W1N4) { src = w1; dst = hw1; }
    else { j -= W1N4; src = w2; dst = hw2; }
    float4 v = ((const float4*)src)[j];
    __half2 h0 = __floats2half2_rn(v.x, v.y);
    __half2 h1 = __floats2half2_rn(v.z, v.w);
    uint2 u;
    u.x = *(unsigned*)&h0;
    u.y = *(unsigned*)&h1;
    ((uint2*)dst)[j] = u;
}

// ---------------------------------------------------------------------------
// TMA-fed HMMA GEMM, free-running warps (proven round 11, unchanged).
// ---------------------------------------------------------------------------
#define NSTAGE   3
#define ABYTES   (128 * 64 * 2)
#define STAGEB   (2 * ABYTES)
#define NKCHUNK  16
#define GEMM_DSMEM (NSTAGE * STAGEB + 1024)

template <bool HALF_OUT>
__global__ __launch_bounds__(256, 2)
void gemm_tma_kernel(const __grid_constant__ CUtensorMap tmA,
                     const __grid_constant__ CUtensorMap tmW,
                     const float* __restrict__ bias,
                     void* __restrict__ Cc, int N)
{
    extern __shared__ char dsm_raw[];
    __shared__ __align__(8) unsigned long long s_mbar[2 * NSTAGE];

    char* smb = (char*)(((uintptr_t)dsm_raw + 1023) & ~(uintptr_t)1023);
    const unsigned base = sptr(smb);

    const int tid  = threadIdx.x;
    const int warp = tid >> 5;
    const int lane = tid & 31;
    const int wm   = warp & 3;
    const int wn   = warp >> 2;
    const int g    = lane >> 2;
    const int q    = lane & 3;
    const int la   = lane & 7;
    const int lb   = (lane >> 3) & 1;
    const int lc   = lane >> 4;
    const int bm   = blockIdx.y * 128;
    const int bn   = blockIdx.x * 128;

    unsigned mf[NSTAGE], me[NSTAGE];
#pragma unroll
    for (int s = 0; s < NSTAGE; s++) {
        mf[s] = sptr(&s_mbar[s]);
        me[s] = sptr(&s_mbar[NSTAGE + s]);
    }

    if (tid == 0) {
#pragma unroll
        for (int s = 0; s < NSTAGE; s++) {
            mbar_init(mf[s], 1);
            mbar_init(me[s], 8);
        }
    }
    __syncthreads();

    if (tid == 0) {
#pragma unroll
        for (int s = 0; s < NSTAGE; s++) {
            mbar_expect(mf[s], STAGEB);
            tma3d(base + s * STAGEB,          &tmA, s * 64, bm, mf[s]);
            tma3d(base + s * STAGEB + ABYTES, &tmW, s * 64, bn, mf[s]);
        }
    }

    float acc[2][8][4];
#pragma unroll
    for (int mt = 0; mt < 2; mt++)
#pragma unroll
        for (int nt = 0; nt < 8; nt++)
#pragma unroll
            for (int c = 0; c < 4; c++) acc[mt][nt][c] = 0.0f;

    for (int c = 0; c < NKCHUNK; c++) {
        const int s = c % NSTAGE;
        const unsigned ph = (unsigned)((c / NSTAGE) & 1);
        mbar_wait(mf[s], ph);

        const unsigned abase = base + s * STAGEB;
        const unsigned bbase = abase + ABYTES;

#pragma unroll
        for (int kk = 0; kk < 4; kk++) {
            unsigned a[2][4];
#pragma unroll
            for (int mt = 0; mt < 2; mt++) {
                int row = wm * 32 + mt * 16 + lb * 8 + la;
                int ch  = (2 * kk + lc) ^ (row & 7);
                ldsm4(a[mt][0], a[mt][1], a[mt][2], a[mt][3],
                      abase + row * 128 + ch * 16);
            }
            unsigned bfr[4][4];
#pragma unroll
            for (int ntp = 0; ntp < 4; ntp++) {
                int row = wn * 64 + ntp * 16 + lc * 8 + la;
                int ch  = (2 * kk + lb) ^ (row & 7);
                ldsm4(bfr[ntp][0], bfr[ntp][1], bfr[ntp][2], bfr[ntp][3],
                      bbase + row * 128 + ch * 16);
            }
#pragma unroll
            for (int mt = 0; mt < 2; mt++)
#pragma unroll
                for (int ntp = 0; ntp < 4; ntp++) {
                    mma16816(acc[mt][2 * ntp],     a[mt][0], a[mt][1], a[mt][2], a[mt][3],
                             bfr[ntp][0], bfr[ntp][1]);
                    mma16816(acc[mt][2 * ntp + 1], a[mt][0], a[mt][1], a[mt][2], a[mt][3],
                             bfr[ntp][2], bfr[ntp][3]);
                }
        }

        if (lane == 0) mbar_arrive(me[s]);

        if (tid == 0) {
            const int cn = c + NSTAGE;
            if (cn < NKCHUNK) {
                mbar_wait(me[s], ph);
                fence_async_shared();
                mbar_expect(mf[s], STAGEB);
                tma3d(abase, &tmA, cn * 64, bm, mf[s]);
                tma3d(bbase, &tmW, cn * 64, bn, mf[s]);
            }
        }
    }

    float2 bv[8];
#pragma unroll
    for (int nt = 0; nt < 8; nt++) {
        int col = bn + wn * 64 + nt * 8 + 2 * q;
        bv[nt].x = bias[col];
        bv[nt].y = bias[col + 1];
    }
#pragma unroll
    for (int mt = 0; mt < 2; mt++) {
        int row = bm + wm * 32 + mt * 16 + g;
#pragma unroll
        for (int nt = 0; nt < 8; nt++) {
            int col = bn + wn * 64 + nt * 8 + 2 * q;
            float x0 = acc[mt][nt][0] + bv[nt].x;
            float y0 = acc[mt][nt][1] + bv[nt].y;
            float x1 = acc[mt][nt][2] + bv[nt].x;
            float y1 = acc[mt][nt][3] + bv[nt].y;
            if (HALF_OUT) {
                __half* O = (__half*)Cc;
                *(__half2*)&O[(size_t)row * N + col]       = __floats2half2_rn(x0, y0);
                *(__half2*)&O[(size_t)(row + 8) * N + col] = __floats2half2_rn(x1, y1);
            } else {
                float* O = (float*)Cc;
                *(float2*)&O[(size_t)row * N + col]       = make_float2(x0, y0);
                *(float2*)&O[(size_t)(row + 8) * N + col] = make_float2(x1, y1);
            }
        }
    }
}

// ---------------------------------------------------------------------------
// Flash attention, FA2 register pipeline + free-running warps + this round:
//  - Q fragments hoisted out of kt loop (loaded once via ldmatrix)
//  - split K/V full barriers (S starts when K arrives; V waited before PV)
//  - exp2-domain softmax (log2e folded into Q scale)
// ---------------------------------------------------------------------------
#define FSTR 72
#define FL_TILEB  (64 * 64 * 2)                    // 8 KB
#define FL_QB     (64 * FSTR * 2)                  // 9 KB
#define FL_DSMEM  (4 * FL_TILEB + FL_QB + 1024)
#define QSCALE_LOG2E 0.1803368801111f              // 0.125 * log2(e)

__global__ __launch_bounds__(128, 4)
void flash_f16_kernel(const __grid_constant__ CUtensorMap tmKV,
                      const __half* __restrict__ qkv, __half* __restrict__ out)
{
    extern __shared__ char fraw[];
    __shared__ __align__(8) unsigned long long s_fmk[2];
    __shared__ __align__(8) unsigned long long s_fmv[2];
    __shared__ __align__(8) unsigned long long s_fe[2];

    char* fb = (char*)(((uintptr_t)fraw + 1023) & ~(uintptr_t)1023);
    const unsigned base = sptr(fb);
    const unsigned kbuf[2] = {base,                base + FL_TILEB};
    const unsigned vbuf[2] = {base + 2 * FL_TILEB, base + 3 * FL_TILEB};
    __half* Qs = (__half*)(fb + 4 * FL_TILEB);
    const unsigned qsb = sptr(Qs);
    const unsigned fmk[2] = {sptr(&s_fmk[0]), sptr(&s_fmk[1])};
    const unsigned fmv[2] = {sptr(&s_fmv[0]), sptr(&s_fmv[1])};
    const unsigned fe[2]  = {sptr(&s_fe[0]),  sptr(&s_fe[1])};

    const int qt   = (int)gridDim.x - 1 - (int)blockIdx.x;  // heavy tiles first
    const int bh   = blockIdx.y;
    const int bb   = bh >> 4;
    const int h    = bh & 15;
    const int tid  = threadIdx.x;
    const int warp = tid >> 5;
    const int lane = tid & 31;
    const int g    = lane >> 2;
    const int q    = lane & 3;
    const int la   = lane & 7;
    const int lb   = (lane >> 3) & 1;
    const int lc   = lane >> 4;
    const int r0   = warp * 16 + g;
    const int r1   = r0 + 8;

    if (tid == 0) {
        mbar_init(fmk[0], 1); mbar_init(fmk[1], 1);
        mbar_init(fmv[0], 1); mbar_init(fmv[1], 1);
        mbar_init(fe[0], 4);  mbar_init(fe[1], 4);
    }

    // Load Q tile (scaled by 0.125*log2e -> exp2-domain scores)
    const __half* qb = qkv + (size_t)(bb * T_) * N_QKV + h * D_;
    const __half2 hs = __floats2half2_rn(QSCALE_LOG2E, QSCALE_LOG2E);
#pragma unroll
    for (int i = 0; i < 4; i++) {
        int idx = tid + i * 128;
        int r   = idx >> 3;
        int c8  = idx & 7;
        uint4 v = *(const uint4*)(qb + (size_t)(qt * 64 + r) * N_QKV + 8 * c8);
        __half2* p = (__half2*)&v;
        p[0] = __hmul2(p[0], hs); p[1] = __hmul2(p[1], hs);
        p[2] = __hmul2(p[2], hs); p[3] = __hmul2(p[3], hs);
        *(uint4*)&Qs[r * FSTR + 8 * c8] = v;
    }
    __syncthreads();   // mbar init + Q stores visible

    if (tid == 0) {
        mbar_expect(fmk[0], FL_TILEB);
        tma3d(kbuf[0], &tmKV, C_ + h * 64,     bb * T_, fmk[0]);
        mbar_expect(fmv[0], FL_TILEB);
        tma3d(vbuf[0], &tmKV, 2 * C_ + h * 64, bb * T_, fmv[0]);
    }

    // Hoist Q fragments (iteration-invariant)
    unsigned qa[4][4];
#pragma unroll
    for (int kk = 0; kk < 4; kk++) {
        int row = warp * 16 + lb * 8 + la;
        int ch  = 2 * kk + lc;
        ldsm4(qa[kk][0], qa[kk][1], qa[kk][2], qa[kk][3],
              qsb + (row * FSTR + ch * 8) * 2);
    }

    float o[8][4];
#pragma unroll
    for (int j = 0; j < 8; j++)
#pragma unroll
        for (int c = 0; c < 4; c++) o[j][c] = 0.0f;
    float m0 = -1e30f, m1 = -1e30f, l0 = 0.0f, l1 = 0.0f;

    for (int kt = 0; kt <= qt; kt++) {
        const int buf = kt & 1;
        const unsigned ph = (unsigned)((kt >> 1) & 1);
        mbar_wait(fmk[buf], ph);

        // Producer: prefetch kt+1 into the other buffer
        if (tid == 0 && kt < qt) {
            const int nb = buf ^ 1;
            if (kt > 0) mbar_wait(fe[nb], (unsigned)(((kt - 1) >> 1) & 1));
            fence_async_shared();
            mbar_expect(fmk[nb], FL_TILEB);
            tma3d(kbuf[nb], &tmKV, C_ + h * 64,     bb * T_ + (kt + 1) * 64, fmk[nb]);
            mbar_expect(fmv[nb], FL_TILEB);
            tma3d(vbuf[nb], &tmKV, 2 * C_ + h * 64, bb * T_ + (kt + 1) * 64, fmv[nb]);
        }

        // ---- S = Q K^T (exp2 domain)
        float s[8][4];
#pragma unroll
        for (int j = 0; j < 8; j++)
#pragma unroll
            for (int c = 0; c < 4; c++) s[j][c] = 0.0f;

#pragma unroll
        for (int kk = 0; kk < 4; kk++) {
#pragma unroll
            for (int ntp = 0; ntp < 4; ntp++) {
                unsigned b0, b1, b2, b3;
                int row = ntp * 16 + lc * 8 + la;
                int ch  = (2 * kk + lb) ^ (row & 7);
                ldsm4(b0, b1, b2, b3, kbuf[buf] + row * 128 + ch * 16);
                mma16816(s[2 * ntp],     qa[kk][0], qa[kk][1], qa[kk][2], qa[kk][3], b0, b1);
                mma16816(s[2 * ntp + 1], qa[kk][0], qa[kk][1], qa[kk][2], qa[kk][3], b2, b3);
            }
        }

        // Causal mask (diagonal tile only)
        if (kt == qt) {
#pragma unroll
            for (int j = 0; j < 8; j++) {
                int c = j * 8 + 2 * q;
                if (c     > r0) s[j][0] = -1e30f;
                if (c + 1 > r0) s[j][1] = -1e30f;
                if (c     > r1) s[j][2] = -1e30f;
                if (c + 1 > r1) s[j][3] = -1e30f;
            }
        }

        // ---- In-warp online softmax (exp2 domain)
        float mx0 = -1e30f, mx1 = -1e30f;
#pragma unroll
        for (int j = 0; j < 8; j++) {
            mx0 = fmaxf(mx0, fmaxf(s[j][0], s[j][1]));
            mx1 = fmaxf(mx1, fmaxf(s[j][2], s[j][3]));
        }
        mx0 = fmaxf(mx0, __shfl_xor_sync(0xffffffffu, mx0, 1));
        mx0 = fmaxf(mx0, __shfl_xor_sync(0xffffffffu, mx0, 2));
        mx1 = fmaxf(mx1, __shfl_xor_sync(0xffffffffu, mx1, 1));
        mx1 = fmaxf(mx1, __shfl_xor_sync(0xffffffffu, mx1, 2));

        float mn0 = fmaxf(m0, mx0);
        float mn1 = fmaxf(m1, mx1);
        float cr0 = exp2f(m0 - mn0);
        float cr1 = exp2f(m1 - mn1);
        m0 = mn0; m1 = mn1;

        float sum0 = 0.0f, sum1 = 0.0f;
        unsigned plo[8], phi[8];
#pragma unroll
        for (int j = 0; j < 8; j++) {
            float p0 = exp2f(s[j][0] - mn0);
            float p1 = exp2f(s[j][1] - mn0);
            float p2 = exp2f(s[j][2] - mn1);
            float p3 = exp2f(s[j][3] - mn1);
            sum0 += p0 + p1;
            sum1 += p2 + p3;
            plo[j] = packh2(p0, p1);
            phi[j] = packh2(p2, p3);
        }
        sum0 += __shfl_xor_sync(0xffffffffu, sum0, 1);
        sum0 += __shfl_xor_sync(0xffffffffu, sum0, 2);
        sum1 += __shfl_xor_sync(0xffffffffu, sum1, 1);
        sum1 += __shfl_xor_sync(0xffffffffu, sum1, 2);
        l0 = l0 * cr0 + sum0;
        l1 = l1 * cr1 + sum1;

#pragma unroll
        for (int j = 0; j < 8; j++) {
            o[j][0] *= cr0; o[j][1] *= cr0;
            o[j][2] *= cr1; o[j][3] *= cr1;
        }

        // ---- O += P V (wait for V arrival first)
        mbar_wait(fmv[buf], ph);
#pragma unroll
        for (int t = 0; t < 4; t++) {
            const unsigned a0 = plo[2 * t];
            const unsigned a1 = phi[2 * t];
            const unsigned a2 = plo[2 * t + 1];
            const unsigned a3 = phi[2 * t + 1];
#pragma unroll
            for (int ntp = 0; ntp < 4; ntp++) {
                unsigned b0, b1, b2, b3;
                int row = t * 16 + lb * 8 + la;
                int ch  = (2 * ntp + lc) ^ (row & 7);
                ldsm4t(b0, b1, b2, b3, vbuf[buf] + row * 128 + ch * 16);
                mma16816(o[2 * ntp],     a0, a1, a2, a3, b0, b1);
                mma16816(o[2 * ntp + 1], a0, a1, a2, a3, b2, b3);
            }
        }

        if (lane == 0) mbar_arrive(fe[buf]);
    }

    // Epilogue
    float il0 = 1.0f / l0;
    float il1 = 1.0f / l1;
    size_t row0 = (size_t)(bb * T_ + qt * 64 + r0);
    size_t row1 = (size_t)(bb * T_ + qt * 64 + r1);
#pragma unroll
    for (int j = 0; j < 8; j++) {
        int col = h * 64 + j * 8 + 2 * q;
        *(__half2*)&out[row0 * C_ + col] = __floats2half2_rn(o[j][0] * il0, o[j][1] * il0);
        *(__half2*)&out[row1 * C_ + col] = __floats2half2_rn(o[j][2] * il1, o[j][3] * il1);
    }
}

// ---------------------------------------------------------------------------
// Host: tensormaps + launch
// ---------------------------------------------------------------------------
typedef CUresult (*PFN_encode)(CUtensorMap*, CUtensorMapDataType, cuuint32_t, void*,
                               const cuuint64_t*, const cuuint64_t*, const cuuint32_t*,
                               const cuuint32_t*, CUtensorMapInterleave, CUtensorMapSwizzle,
                               CUtensorMapL2promotion, CUtensorMapFloatOOBfill);

static void make_map(PFN_encode enc, CUtensorMap* tm, void* ptr,
                     unsigned long long cols, unsigned long long rows,
                     unsigned bx, unsigned by) {
    cuuint64_t dims[3]    = {cols, rows, 1};
    cuuint64_t strides[2] = {cols * 2, rows * cols * 2};
    cuuint32_t box[3]     = {bx, by, 1};
    cuuint32_t es[3]      = {1, 1, 1};
    enc(tm, CU_TENSOR_MAP_DATA_TYPE_FLOAT16, 3, ptr, dims, strides, box, es,
        CU_TENSOR_MAP_INTERLEAVE_NONE, CU_TENSOR_MAP_SWIZZLE_128B,
        CU_TENSOR_MAP_L2_PROMOTION_L2_128B, CU_TENSOR_MAP_FLOAT_OOB_FILL_NONE);
}

extern "C" void kernel_launch(void* const* d_in, const int* in_sizes, int n_in,
                              void* d_out, int out_size)
{
    const float* x      = (const float*)d_in[0];
    const float* W_qkv  = (const float*)d_in[1];
    const float* b_qkv  = (const float*)d_in[2];
    const float* W_proj = (const float*)d_in[3];
    const float* b_proj = (const float*)d_in[4];
    float* out = (float*)d_out;

    __half *hx, *hw1, *hw2, *qkv, *att;
    cudaGetSymbolAddress((void**)&hx,  g_hx);
    cudaGetSymbolAddress((void**)&hw1, g_hw1);
    cudaGetSymbolAddress((void**)&hw2, g_hw2);
    cudaGetSymbolAddress((void**)&qkv, g_qkv);
    cudaGetSymbolAddress((void**)&att, g_att);

    void* fnp = nullptr;
    cudaDriverEntryPointQueryResult qr;
    cudaGetDriverEntryPointByVersion("cuTensorMapEncodeTiled", &fnp, 12000,
                                     cudaEnableDefault, &qr);
    PFN_encode enc = (PFN_encode)fnp;

    CUtensorMap tmX, tmW1, tmAtt, tmW2, tmKV;
    make_map(enc, &tmX,   hx,  C_,    M_,    64, 128);
    make_map(enc, &tmW1,  hw1, C_,    N_QKV, 64, 128);
    make_map(enc, &tmAtt, att, C_,    M_,    64, 128);
    make_map(enc, &tmW2,  hw2, C_,    C_,    64, 128);
    make_map(enc, &tmKV,  qkv, N_QKV, M_,    64, 64);

    // 0) fused fp32 -> fp16 converts (single launch)
    f2h_all_kernel<<<(CVT_TOTAL + 255) / 256, 256>>>(x, W_qkv, W_proj, hx, hw1, hw2);

    // 1) qkv = x @ W_qkv^T + b_qkv (half out)
    cudaFuncSetAttribute((const void*)gemm_tma_kernel<true>,
                         cudaFuncAttributeMaxDynamicSharedMemorySize, GEMM_DSMEM);
    gemm_tma_kernel<true><<<dim3(N_QKV / 128, M_ / 128), 256, GEMM_DSMEM>>>(
        tmX, tmW1, b_qkv, qkv, N_QKV);

    // 2) flash attention
    cudaFuncSetAttribute(flash_f16_kernel,
                         cudaFuncAttributeMaxDynamicSharedMemorySize, FL_DSMEM);
    flash_f16_kernel<<<dim3(T_ / 64, B_ * H_), 128, FL_DSMEM>>>(tmKV, qkv, att);

    // 3) out = att @ W_proj^T + b_proj (float out)
    cudaFuncSetAttribute((const void*)gemm_tma_kernel<false>,
                         cudaFuncAttributeMaxDynamicSharedMemorySize, GEMM_DSMEM);
    gemm_tma_kernel<false><<<dim3(C_ / 128, M_ / 128), 256, GEMM_DSMEM>>>(
        tmAtt, tmW2, b_proj, out, C_);
}

// round 13
// speedup vs baseline: 1.4092x; 1.0034x over previous
#include <cuda_runtime.h>
#include <cuda.h>
#include <cuda_fp16.h>
#include <math.h>
#include <stdint.h>

// ---------------------------------------------------------------------------
// Problem constants
// ---------------------------------------------------------------------------
#define B_    4
#define T_    2048
#define C_    1024
#define H_    16
#define D_    64
#define M_    (B_ * T_)        // 8192
#define N_QKV (3 * C_)         // 3072

// Scratch (__device__ globals; allocation-free rule)
__device__ __half g_hx[M_ * C_];
__device__ __half g_hw1[N_QKV * C_];
__device__ __half g_hw2[C_ * C_];
__device__ __half g_qkv[(size_t)M_ * N_QKV];
__device__ __half g_att[M_ * C_];

// ---------------------------------------------------------------------------
// PTX helpers
// ---------------------------------------------------------------------------
__device__ __forceinline__ unsigned sptr(const void* p) {
    return (unsigned)__cvta_generic_to_shared(p);
}
__device__ __forceinline__ void ldsm4(unsigned& r0, unsigned& r1,
                                      unsigned& r2, unsigned& r3, unsigned a) {
    asm volatile("ldmatrix.sync.aligned.m8n8.x4.shared.b16 {%0,%1,%2,%3},[%4];"
                 : "=r"(r0), "=r"(r1), "=r"(r2), "=r"(r3) : "r"(a));
}
__device__ __forceinline__ void ldsm4t(unsigned& r0, unsigned& r1,
                                       unsigned& r2, unsigned& r3, unsigned a) {
    asm volatile("ldmatrix.sync.aligned.m8n8.x4.trans.shared.b16 {%0,%1,%2,%3},[%4];"
                 : "=r"(r0), "=r"(r1), "=r"(r2), "=r"(r3) : "r"(a));
}
__device__ __forceinline__ void mma16816(float* d,
                                         unsigned a0, unsigned a1, unsigned a2, unsigned a3,
                                         unsigned b0, unsigned b1) {
    asm volatile(
        "mma.sync.aligned.m16n8k16.row.col.f32.f16.f16.f32 "
        "{%0,%1,%2,%3},{%4,%5,%6,%7},{%8,%9},{%0,%1,%2,%3};"
        : "+f"(d[0]), "+f"(d[1]), "+f"(d[2]), "+f"(d[3])
        : "r"(a0), "r"(a1), "r"(a2), "r"(a3), "r"(b0), "r"(b1));
}
__device__ __forceinline__ void mbar_init(unsigned a, unsigned cnt) {
    asm volatile("mbarrier.init.shared.b64 [%0], %1;" :: "r"(a), "r"(cnt) : "memory");
}
__device__ __forceinline__ void mbar_expect(unsigned a, unsigned bytes) {
    asm volatile("mbarrier.arrive.expect_tx.shared.b64 _, [%0], %1;"
                 :: "r"(a), "r"(bytes) : "memory");
}
__device__ __forceinline__ void mbar_arrive(unsigned a) {
    asm volatile("mbarrier.arrive.shared.b64 _, [%0];" :: "r"(a) : "memory");
}
__device__ __forceinline__ void mbar_wait(unsigned a, unsigned parity) {
    asm volatile(
        "{\n\t.reg .pred P;\n\t"
        "W%=:\n\t"
        "mbarrier.try_wait.parity.acquire.cta.shared::cta.b64 P, [%0], %1, 0x989680;\n\t"
        "@P bra.uni D%=;\n\t"
        "bra.uni W%=;\n\t"
        "D%=:\n\t}"
        :: "r"(a), "r"(parity) : "memory");
}
__device__ __forceinline__ void tma3d(unsigned dst, const void* tm, int x, int y, unsigned mbar) {
    asm volatile(
        "cp.async.bulk.tensor.3d.shared::cta.global.tile.mbarrier::complete_tx::bytes "
        "[%0], [%1, {%2, %3, %4}], [%5];"
        :: "r"(dst), "l"(tm), "r"(x), "r"(y), "r"(0), "r"(mbar) : "memory");
}
__device__ __forceinline__ void fence_async_shared() {
    asm volatile("fence.proxy.async.shared::cta;" ::: "memory");
}
__device__ __forceinline__ unsigned packh2(float x, float y) {
    __half2 h = __floats2half2_rn(x, y);
    return *(unsigned*)&h;
}

// ---------------------------------------------------------------------------
// Fused fp32 -> fp16 convert for x, W_qkv, W_proj (one launch)
// ---------------------------------------------------------------------------
#define XN4  (M_ * C_ / 4)
#define W1N4 (N_QKV * C_ / 4)
#define W2N4 (C_ * C_ / 4)
#define CVT_TOTAL (XN4 + W1N4 + W2N4)

__global__ void f2h_all_kernel(const float* __restrict__ x,
                               const float* __restrict__ w1,
                               const float* __restrict__ w2,
                               __half* __restrict__ hx,
                               __half* __restrict__ hw1,
                               __half* __restrict__ hw2) {
    int i = blockIdx.x * blockDim.x + threadIdx.x;
    if (i >= CVT_TOTAL) return;
    const float* src;
    __half* dst;
    int j = i;
    if (j < XN4) { src = x; dst = hx; }
    else if ((j -= XN4) < W1N4) { src = w1; dst = hw1; }
    else { j -= W1N4; src = w2; dst = hw2; }
    float4 v = ((const float4*)src)[j];
    __half2 h0 = __floats2half2_rn(v.x, v.y);
    __half2 h1 = __floats2half2_rn(v.z, v.w);
    uint2 u;
    u.x = *(unsigned*)&h0;
    u.y = *(unsigned*)&h1;
    ((uint2*)dst)[j] = u;
}

// ---------------------------------------------------------------------------
// TMA-fed HMMA GEMM, free-running warps + ROTATING producer (warp c%8).
// ---------------------------------------------------------------------------
#define NSTAGE   3
#define ABYTES   (128 * 64 * 2)
#define STAGEB   (2 * ABYTES)
#define NKCHUNK  16
#define GEMM_DSMEM (NSTAGE * STAGEB + 1024)

template <bool HALF_OUT>
__global__ __launch_bounds__(256, 2)
void gemm_tma_kernel(const __grid_constant__ CUtensorMap tmA,
                     const __grid_constant__ CUtensorMap tmW,
                     const float* __restrict__ bias,
                     void* __restrict__ Cc, int N)
{
    extern __shared__ char dsm_raw[];
    __shared__ __align__(8) unsigned long long s_mbar[2 * NSTAGE];

    char* smb = (char*)(((uintptr_t)dsm_raw + 1023) & ~(uintptr_t)1023);
    const unsigned base = sptr(smb);

    const int tid  = threadIdx.x;
    const int warp = tid >> 5;
    const int lane = tid & 31;
    const int wm   = warp & 3;
    const int wn   = warp >> 2;
    const int g    = lane >> 2;
    const int q    = lane & 3;
    const int la   = lane & 7;
    const int lb   = (lane >> 3) & 1;
    const int lc   = lane >> 4;
    const int bm   = blockIdx.y * 128;
    const int bn   = blockIdx.x * 128;

    unsigned mf[NSTAGE], me[NSTAGE];
#pragma unroll
    for (int s = 0; s < NSTAGE; s++) {
        mf[s] = sptr(&s_mbar[s]);
        me[s] = sptr(&s_mbar[NSTAGE + s]);
    }

    if (tid == 0) {
#pragma unroll
        for (int s = 0; s < NSTAGE; s++) {
            mbar_init(mf[s], 1);
            mbar_init(me[s], 8);
        }
    }
    __syncthreads();

    if (tid == 0) {
#pragma unroll
        for (int s = 0; s < NSTAGE; s++) {
            mbar_expect(mf[s], STAGEB);
            tma3d(base + s * STAGEB,          &tmA, s * 64, bm, mf[s]);
            tma3d(base + s * STAGEB + ABYTES, &tmW, s * 64, bn, mf[s]);
        }
    }

    float acc[2][8][4];
#pragma unroll
    for (int mt = 0; mt < 2; mt++)
#pragma unroll
        for (int nt = 0; nt < 8; nt++)
#pragma unroll
            for (int c = 0; c < 4; c++) acc[mt][nt][c] = 0.0f;

    for (int c = 0; c < NKCHUNK; c++) {
        const int s = c % NSTAGE;
        const unsigned ph = (unsigned)((c / NSTAGE) & 1);
        mbar_wait(mf[s], ph);

        const unsigned abase = base + s * STAGEB;
        const unsigned bbase = abase + ABYTES;

#pragma unroll
        for (int kk = 0; kk < 4; kk++) {
            unsigned a[2][4];
#pragma unroll
            for (int mt = 0; mt < 2; mt++) {
                int row = wm * 32 + mt * 16 + lb * 8 + la;
                int ch  = (2 * kk + lc) ^ (row & 7);
                ldsm4(a[mt][0], a[mt][1], a[mt][2], a[mt][3],
                      abase + row * 128 + ch * 16);
            }
            unsigned bfr[4][4];
#pragma unroll
            for (int ntp = 0; ntp < 4; ntp++) {
                int row = wn * 64 + ntp * 16 + lc * 8 + la;
                int ch  = (2 * kk + lb) ^ (row & 7);
                ldsm4(bfr[ntp][0], bfr[ntp][1], bfr[ntp][2], bfr[ntp][3],
                      bbase + row * 128 + ch * 16);
            }
#pragma unroll
            for (int mt = 0; mt < 2; mt++)
#pragma unroll
                for (int ntp = 0; ntp < 4; ntp++) {
                    mma16816(acc[mt][2 * ntp],     a[mt][0], a[mt][1], a[mt][2], a[mt][3],
                             bfr[ntp][0], bfr[ntp][1]);
                    mma16816(acc[mt][2 * ntp + 1], a[mt][0], a[mt][1], a[mt][2], a[mt][3],
                             bfr[ntp][2], bfr[ntp][3]);
                }
        }

        // This warp is done reading stage s.
        if (lane == 0) mbar_arrive(me[s]);

        // Rotating producer: warp (c % 8) re-arms stage s for chunk c+NSTAGE.
        if (warp == (c & 7) && lane == 0) {
            const int cn = c + NSTAGE;
            if (cn < NKCHUNK) {
                mbar_wait(me[s], ph);     // all 8 warps done with stage s
                fence_async_shared();
                mbar_expect(mf[s], STAGEB);
                tma3d(abase, &tmA, cn * 64, bm, mf[s]);
                tma3d(bbase, &tmW, cn * 64, bn, mf[s]);
            }
        }
    }

    float2 bv[8];
#pragma unroll
    for (int nt = 0; nt < 8; nt++) {
        int col = bn + wn * 64 + nt * 8 + 2 * q;
        bv[nt].x = bias[col];
        bv[nt].y = bias[col + 1];
    }
#pragma unroll
    for (int mt = 0; mt < 2; mt++) {
        int row = bm + wm * 32 + mt * 16 + g;
#pragma unroll
        for (int nt = 0; nt < 8; nt++) {
            int col = bn + wn * 64 + nt * 8 + 2 * q;
            float x0 = acc[mt][nt][0] + bv[nt].x;
            float y0 = acc[mt][nt][1] + bv[nt].y;
            float x1 = acc[mt][nt][2] + bv[nt].x;
            float y1 = acc[mt][nt][3] + bv[nt].y;
            if (HALF_OUT) {
                __half* O = (__half*)Cc;
                *(__half2*)&O[(size_t)row * N + col]       = __floats2half2_rn(x0, y0);
                *(__half2*)&O[(size_t)(row + 8) * N + col] = __floats2half2_rn(x1, y1);
            } else {
                float* O = (float*)Cc;
                *(float2*)&O[(size_t)row * N + col]       = make_float2(x0, y0);
                *(float2*)&O[(size_t)(row + 8) * N + col] = make_float2(x1, y1);
            }
        }
    }
}

// ---------------------------------------------------------------------------
// Flash attention: FA2 register pipeline, free-running warps, split K/V
// barriers, exp2 softmax, hoisted Q frags, ROTATING producer (warp kt&3),
// prefetch issued before the K-arrival wait.
// ---------------------------------------------------------------------------
#define FSTR 72
#define FL_TILEB  (64 * 64 * 2)                    // 8 KB
#define FL_QB     (64 * FSTR * 2)                  // 9 KB
#define FL_DSMEM  (4 * FL_TILEB + FL_QB + 1024)
#define QSCALE_LOG2E 0.1803368801111f              // 0.125 * log2(e)

__global__ __launch_bounds__(128, 4)
void flash_f16_kernel(const __grid_constant__ CUtensorMap tmKV,
                      const __half* __restrict__ qkv, __half* __restrict__ out)
{
    extern __shared__ char fraw[];
    __shared__ __align__(8) unsigned long long s_fmk[2];
    __shared__ __align__(8) unsigned long long s_fmv[2];
    __shared__ __align__(8) unsigned long long s_fe[2];

    char* fb = (char*)(((uintptr_t)fraw + 1023) & ~(uintptr_t)1023);
    const unsigned base = sptr(fb);
    const unsigned kbuf[2] = {base,                base + FL_TILEB};
    const unsigned vbuf[2] = {base + 2 * FL_TILEB, base + 3 * FL_TILEB};
    __half* Qs = (__half*)(fb + 4 * FL_TILEB);
    const unsigned qsb = sptr(Qs);
    const unsigned fmk[2] = {sptr(&s_fmk[0]), sptr(&s_fmk[1])};
    const unsigned fmv[2] = {sptr(&s_fmv[0]), sptr(&s_fmv[1])};
    const unsigned fe[2]  = {sptr(&s_fe[0]),  sptr(&s_fe[1])};

    const int qt   = (int)gridDim.x - 1 - (int)blockIdx.x;  // heavy tiles first
    const int bh   = blockIdx.y;
    const int bb   = bh >> 4;
    const int h    = bh & 15;
    const int tid  = threadIdx.x;
    const int warp = tid >> 5;
    const int lane = tid & 31;
    const int g    = lane >> 2;
    const int q    = lane & 3;
    const int la   = lane & 7;
    const int lb   = (lane >> 3) & 1;
    const int lc   = lane >> 4;
    const int r0   = warp * 16 + g;
    const int r1   = r0 + 8;

    if (tid == 0) {
        mbar_init(fmk[0], 1); mbar_init(fmk[1], 1);
        mbar_init(fmv[0], 1); mbar_init(fmv[1], 1);
        mbar_init(fe[0], 4);  mbar_init(fe[1], 4);
    }

    // Load Q tile (scaled by 0.125*log2e -> exp2-domain scores)
    const __half* qb = qkv + (size_t)(bb * T_) * N_QKV + h * D_;
    const __half2 hs = __floats2half2_rn(QSCALE_LOG2E, QSCALE_LOG2E);
#pragma unroll
    for (int i = 0; i < 4; i++) {
        int idx = tid + i * 128;
        int r   = idx >> 3;
        int c8  = idx & 7;
        uint4 v = *(const uint4*)(qb + (size_t)(qt * 64 + r) * N_QKV + 8 * c8);
        __half2* p = (__half2*)&v;
        p[0] = __hmul2(p[0], hs); p[1] = __hmul2(p[1], hs);
        p[2] = __hmul2(p[2], hs); p[3] = __hmul2(p[3], hs);
        *(uint4*)&Qs[r * FSTR + 8 * c8] = v;
    }
    __syncthreads();   // mbar init + Q stores visible

    if (tid == 0) {
        mbar_expect(fmk[0], FL_TILEB);
        tma3d(kbuf[0], &tmKV, C_ + h * 64,     bb * T_, fmk[0]);
        mbar_expect(fmv[0], FL_TILEB);
        tma3d(vbuf[0], &tmKV, 2 * C_ + h * 64, bb * T_, fmv[0]);
    }

    // Hoist Q fragments (iteration-invariant)
    unsigned qa[4][4];
#pragma unroll
    for (int kk = 0; kk < 4; kk++) {
        int row = warp * 16 + lb * 8 + la;
        int ch  = 2 * kk + lc;
        ldsm4(qa[kk][0], qa[kk][1], qa[kk][2], qa[kk][3],
              qsb + (row * FSTR + ch * 8) * 2);
    }

    float o[8][4];
#pragma unroll
    for (int j = 0; j < 8; j++)
#pragma unroll
        for (int c = 0; c < 4; c++) o[j][c] = 0.0f;
    float m0 = -1e30f, m1 = -1e30f, l0 = 0.0f, l1 = 0.0f;

    for (int kt = 0; kt <= qt; kt++) {
        const int buf = kt & 1;
        const unsigned ph = (unsigned)((kt >> 1) & 1);

        // Rotating producer: warp (kt & 3) prefetches kt+1 into the other
        // buffer. Depends only on fe[nb] (readers of iteration kt-1), so it
        // is issued BEFORE waiting for this iteration's K arrival.
        if (warp == (kt & 3) && lane == 0 && kt < qt) {
            const int nb = buf ^ 1;
            if (kt > 0) mbar_wait(fe[nb], (unsigned)(((kt - 1) >> 1) & 1));
            fence_async_shared();
            mbar_expect(fmk[nb], FL_TILEB);
            tma3d(kbuf[nb], &tmKV, C_ + h * 64,     bb * T_ + (kt + 1) * 64, fmk[nb]);
            mbar_expect(fmv[nb], FL_TILEB);
            tma3d(vbuf[nb], &tmKV, 2 * C_ + h * 64, bb * T_ + (kt + 1) * 64, fmv[nb]);
        }

        mbar_wait(fmk[buf], ph);

        // ---- S = Q K^T (exp2 domain)
        float s[8][4];
#pragma unroll
        for (int j = 0; j < 8; j++)
#pragma unroll
            for (int c = 0; c < 4; c++) s[j][c] = 0.0f;

#pragma unroll
        for (int kk = 0; kk < 4; kk++) {
#pragma unroll
            for (int ntp = 0; ntp < 4; ntp++) {
                unsigned b0, b1, b2, b3;
                int row = ntp * 16 + lc * 8 + la;
                int ch  = (2 * kk + lb) ^ (row & 7);
                ldsm4(b0, b1, b2, b3, kbuf[buf] + row * 128 + ch * 16);
                mma16816(s[2 * ntp],     qa[kk][0], qa[kk][1], qa[kk][2], qa[kk][3], b0, b1);
                mma16816(s[2 * ntp + 1], qa[kk][0], qa[kk][1], qa[kk][2], qa[kk][3], b2, b3);
            }
        }

        // Causal mask (diagonal tile only)
        if (kt == qt) {
#pragma unroll
            for (int j = 0; j < 8; j++) {
                int c = j * 8 + 2 * q;
                if (c     > r0) s[j][0] = -1e30f;
                if (c + 1 > r0) s[j][1] = -1e30f;
                if (c     > r1) s[j][2] = -1e30f;
                if (c + 1 > r1) s[j][3] = -1e30f;
            }
        }

        // ---- In-warp online softmax (exp2 domain)
        float mx0 = -1e30f, mx1 = -1e30f;
#pragma unroll
        for (int j = 0; j < 8; j++) {
            mx0 = fmaxf(mx0, fmaxf(s[j][0], s[j][1]));
            mx1 = fmaxf(mx1, fmaxf(s[j][2], s[j][3]));
        }
        mx0 = fmaxf(mx0, __shfl_xor_sync(0xffffffffu, mx0, 1));
        mx0 = fmaxf(mx0, __shfl_xor_sync(0xffffffffu, mx0, 2));
        mx1 = fmaxf(mx1, __shfl_xor_sync(0xffffffffu, mx1, 1));
        mx1 = fmaxf(mx1, __shfl_xor_sync(0xffffffffu, mx1, 2));

        float mn0 = fmaxf(m0, mx0);
        float mn1 = fmaxf(m1, mx1);
        float cr0 = exp2f(m0 - mn0);
        float cr1 = exp2f(m1 - mn1);
        m0 = mn0; m1 = mn1;

        float sum0 = 0.0f, sum1 = 0.0f;
        unsigned plo[8], phi[8];
#pragma unroll
        for (int j = 0; j < 8; j++) {
            float p0 = exp2f(s[j][0] - mn0);
            float p1 = exp2f(s[j][1] - mn0);
            float p2 = exp2f(s[j][2] - mn1);
            float p3 = exp2f(s[j][3] - mn1);
            sum0 += p0 + p1;
            sum1 += p2 + p3;
            plo[j] = packh2(p0, p1);
            phi[j] = packh2(p2, p3);
        }
        sum0 += __shfl_xor_sync(0xffffffffu, sum0, 1);
        sum0 += __shfl_xor_sync(0xffffffffu, sum0, 2);
        sum1 += __shfl_xor_sync(0xffffffffu, sum1, 1);
        sum1 += __shfl_xor_sync(0xffffffffu, sum1, 2);
        l0 = l0 * cr0 + sum0;
        l1 = l1 * cr1 + sum1;

#pragma unroll
        for (int j = 0; j < 8; j++) {
            o[j][0] *= cr0; o[j][1] *= cr0;
            o[j][2] *= cr1; o[j][3] *= cr1;
        }

        // ---- O += P V (wait for V arrival first)
        mbar_wait(fmv[buf], ph);
#pragma unroll
        for (int t = 0; t < 4; t++) {
            const unsigned a0 = plo[2 * t];
            const unsigned a1 = phi[2 * t];
            const unsigned a2 = plo[2 * t + 1];
            const unsigned a3 = phi[2 * t + 1];
#pragma unroll
            for (int ntp = 0; ntp < 4; ntp++) {
                unsigned b0, b1, b2, b3;
                int row = t * 16 + lb * 8 + la;
                int ch  = (2 * ntp + lc) ^ (row & 7);
                ldsm4t(b0, b1, b2, b3, vbuf[buf] + row * 128 + ch * 16);
                mma16816(o[2 * ntp],     a0, a1, a2, a3, b0, b1);
                mma16816(o[2 * ntp + 1], a0, a1, a2, a3, b2, b3);
            }
        }

        if (lane == 0) mbar_arrive(fe[buf]);
    }

    // Epilogue
    float il0 = 1.0f / l0;
    float il1 = 1.0f / l1;
    size_t row0 = (size_t)(bb * T_ + qt * 64 + r0);
    size_t row1 = (size_t)(bb * T_ + qt * 64 + r1);
#pragma unroll
    for (int j = 0; j < 8; j++) {
        int col = h * 64 + j * 8 + 2 * q;
        *(__half2*)&out[row0 * C_ + col] = __floats2half2_rn(o[j][0] * il0, o[j][1] * il0);
        *(__half2*)&out[row1 * C_ + col] = __floats2half2_rn(o[j][2] * il1, o[j][3] * il1);
    }
}

// ---------------------------------------------------------------------------
// Host: tensormaps + launch
// ---------------------------------------------------------------------------
typedef CUresult (*PFN_encode)(CUtensorMap*, CUtensorMapDataType, cuuint32_t, void*,
                               const cuuint64_t*, const cuuint64_t*, const cuuint32_t*,
                               const cuuint32_t*, CUtensorMapInterleave, CUtensorMapSwizzle,
                               CUtensorMapL2promotion, CUtensorMapFloatOOBfill);

static void make_map(PFN_encode enc, CUtensorMap* tm, void* ptr,
                     unsigned long long cols, unsigned long long rows,
                     unsigned bx, unsigned by) {
    cuuint64_t dims[3]    = {cols, rows, 1};
    cuuint64_t strides[2] = {cols * 2, rows * cols * 2};
    cuuint32_t box[3]     = {bx, by, 1};
    cuuint32_t es[3]      = {1, 1, 1};
    enc(tm, CU_TENSOR_MAP_DATA_TYPE_FLOAT16, 3, ptr, dims, strides, box, es,
        CU_TENSOR_MAP_INTERLEAVE_NONE, CU_TENSOR_MAP_SWIZZLE_128B,
        CU_TENSOR_MAP_L2_PROMOTION_L2_128B, CU_TENSOR_MAP_FLOAT_OOB_FILL_NONE);
}

extern "C" void kernel_launch(void* const* d_in, const int* in_sizes, int n_in,
                              void* d_out, int out_size)
{
    const float* x      = (const float*)d_in[0];
    const float* W_qkv  = (const float*)d_in[1];
    const float* b_qkv  = (const float*)d_in[2];
    const float* W_proj = (const float*)d_in[3];
    const float* b_proj = (const float*)d_in[4];
    float* out = (float*)d_out;

    __half *hx, *hw1, *hw2, *qkv, *att;
    cudaGetSymbolAddress((void**)&hx,  g_hx);
    cudaGetSymbolAddress((void**)&hw1, g_hw1);
    cudaGetSymbolAddress((void**)&hw2, g_hw2);
    cudaGetSymbolAddress((void**)&qkv, g_qkv);
    cudaGetSymbolAddress((void**)&att, g_att);

    void* fnp = nullptr;
    cudaDriverEntryPointQueryResult qr;
    cudaGetDriverEntryPointByVersion("cuTensorMapEncodeTiled", &fnp, 12000,
                                     cudaEnableDefault, &qr);
    PFN_encode enc = (PFN_encode)fnp;

    CUtensorMap tmX, tmW1, tmAtt, tmW2, tmKV;
    make_map(enc, &tmX,   hx,  C_,    M_,    64, 128);
    make_map(enc, &tmW1,  hw1, C_,    N_QKV, 64, 128);
    make_map(enc, &tmAtt, att, C_,    M_,    64, 128);
    make_map(enc, &tmW2,  hw2, C_,    C_,    64, 128);
    make_map(enc, &tmKV,  qkv, N_QKV, M_,    64, 64);

    // 0) fused fp32 -> fp16 converts (single launch)
    f2h_all_kernel<<<(CVT_TOTAL + 255) / 256, 256>>>(x, W_qkv, W_proj, hx, hw1, hw2);

    // 1) qkv = x @ W_qkv^T + b_qkv (half out)
    cudaFuncSetAttribute((const void*)gemm_tma_kernel<true>,
                         cudaFuncAttributeMaxDynamicSharedMemorySize, GEMM_DSMEM);
    gemm_tma_kernel<true><<<dim3(N_QKV / 128, M_ / 128), 256, GEMM_DSMEM>>>(
        tmX, tmW1, b_qkv, qkv, N_QKV);

    // 2) flash attention
    cudaFuncSetAttribute(flash_f16_kernel,
                         cudaFuncAttributeMaxDynamicSharedMemorySize, FL_DSMEM);
    flash_f16_kernel<<<dim3(T_ / 64, B_ * H_), 128, FL_DSMEM>>>(tmKV, qkv, att);

    // 3) out = att @ W_proj^T + b_proj (float out)
    cudaFuncSetAttribute((const void*)gemm_tma_kernel<false>,
                         cudaFuncAttributeMaxDynamicSharedMemorySize, GEMM_DSMEM);
    gemm_tma_kernel<false><<<dim3(C_ / 128, M_ / 128), 256, GEMM_DSMEM>>>(
        tmAtt, tmW2, b_proj, out, C_);
}

// round 14
// speedup vs baseline: 1.4595x; 1.0357x over previous
#include <cuda_runtime.h>
#include <cuda.h>
#include <cuda_fp16.h>
#include <math.h>
#include <stdint.h>

// ---------------------------------------------------------------------------
// Problem constants
// ---------------------------------------------------------------------------
#define B_    4
#define T_    2048
#define C_    1024
#define H_    16
#define D_    64
#define M_    (B_ * T_)        // 8192
#define N_QKV (3 * C_)         // 3072

// Scratch (__device__ globals; allocation-free rule)
__device__ __half g_hx[M_ * C_];
__device__ __half g_hw1[N_QKV * C_];
__device__ __half g_hw2[C_ * C_];
__device__ __half g_qkv[(size_t)M_ * N_QKV];
__device__ __half g_att[M_ * C_];

// ---------------------------------------------------------------------------
// PTX helpers
// ---------------------------------------------------------------------------
__device__ __forceinline__ unsigned sptr(const void* p) {
    return (unsigned)__cvta_generic_to_shared(p);
}
__device__ __forceinline__ void ldsm4(unsigned& r0, unsigned& r1,
                                      unsigned& r2, unsigned& r3, unsigned a) {
    asm volatile("ldmatrix.sync.aligned.m8n8.x4.shared.b16 {%0,%1,%2,%3},[%4];"
                 : "=r"(r0), "=r"(r1), "=r"(r2), "=r"(r3) : "r"(a));
}
__device__ __forceinline__ void ldsm4t(unsigned& r0, unsigned& r1,
                                       unsigned& r2, unsigned& r3, unsigned a) {
    asm volatile("ldmatrix.sync.aligned.m8n8.x4.trans.shared.b16 {%0,%1,%2,%3},[%4];"
                 : "=r"(r0), "=r"(r1), "=r"(r2), "=r"(r3) : "r"(a));
}
__device__ __forceinline__ void mma16816(float* d,
                                         unsigned a0, unsigned a1, unsigned a2, unsigned a3,
                                         unsigned b0, unsigned b1) {
    asm volatile(
        "mma.sync.aligned.m16n8k16.row.col.f32.f16.f16.f32 "
        "{%0,%1,%2,%3},{%4,%5,%6,%7},{%8,%9},{%0,%1,%2,%3};"
        : "+f"(d[0]), "+f"(d[1]), "+f"(d[2]), "+f"(d[3])
        : "r"(a0), "r"(a1), "r"(a2), "r"(a3), "r"(b0), "r"(b1));
}
__device__ __forceinline__ void mbar_init(unsigned a, unsigned cnt) {
    asm volatile("mbarrier.init.shared.b64 [%0], %1;" :: "r"(a), "r"(cnt) : "memory");
}
__device__ __forceinline__ void mbar_expect(unsigned a, unsigned bytes) {
    asm volatile("mbarrier.arrive.expect_tx.shared.b64 _, [%0], %1;"
                 :: "r"(a), "r"(bytes) : "memory");
}
__device__ __forceinline__ void mbar_arrive(unsigned a) {
    asm volatile("mbarrier.arrive.shared.b64 _, [%0];" :: "r"(a) : "memory");
}
__device__ __forceinline__ void mbar_wait(unsigned a, unsigned parity) {
    asm volatile(
        "{\n\t.reg .pred P;\n\t"
        "W%=:\n\t"
        "mbarrier.try_wait.parity.acquire.cta.shared::cta.b64 P, [%0], %1, 0x989680;\n\t"
        "@P bra.uni D%=;\n\t"
        "bra.uni W%=;\n\t"
        "D%=:\n\t}"
        :: "r"(a), "r"(parity) : "memory");
}
__device__ __forceinline__ void tma3d(unsigned dst, const void* tm, int x, int y, unsigned mbar) {
    asm volatile(
        "cp.async.bulk.tensor.3d.shared::cta.global.tile.mbarrier::complete_tx::bytes "
        "[%0], [%1, {%2, %3, %4}], [%5];"
        :: "r"(dst), "l"(tm), "r"(x), "r"(y), "r"(0), "r"(mbar) : "memory");
}
__device__ __forceinline__ void fence_async_shared() {
    asm volatile("fence.proxy.async.shared::cta;" ::: "memory");
}
__device__ __forceinline__ unsigned packh2(float x, float y) {
    __half2 h = __floats2half2_rn(x, y);
    return *(unsigned*)&h;
}
__device__ __forceinline__ float ex2(float x) {
    float y;
    asm("ex2.approx.ftz.f32 %0, %1;" : "=f"(y) : "f"(x));
    return y;
}

// ---------------------------------------------------------------------------
// Fused fp32 -> fp16 convert for x, W_qkv, W_proj (one launch)
// ---------------------------------------------------------------------------
#define XN4  (M_ * C_ / 4)
#define W1N4 (N_QKV * C_ / 4)
#define W2N4 (C_ * C_ / 4)
#define CVT_TOTAL (XN4 + W1N4 + W2N4)

__global__ void f2h_all_kernel(const float* __restrict__ x,
                               const float* __restrict__ w1,
                               const float* __restrict__ w2,
                               __half* __restrict__ hx,
                               __half* __restrict__ hw1,
                               __half* __restrict__ hw2) {
    int i = blockIdx.x * blockDim.x + threadIdx.x;
    if (i >= CVT_TOTAL) return;
    const float* src;
    __half* dst;
    int j = i;
    if (j < XN4) { src = x; dst = hx; }
    else if ((j -= XN4) < W1N4) { src = w1; dst = hw1; }
    else { j -= W1N4; src = w2; dst = hw2; }
    float4 v = ((const float4*)src)[j];
    __half2 h0 = __floats2half2_rn(v.x, v.y);
    __half2 h1 = __floats2half2_rn(v.z, v.w);
    uint2 u;
    u.x = *(unsigned*)&h0;
    u.y = *(unsigned*)&h1;
    ((uint2*)dst)[j] = u;
}

// ---------------------------------------------------------------------------
// TMA-fed HMMA GEMM, free-running warps + rotating producer (frozen).
// ---------------------------------------------------------------------------
#define NSTAGE   3
#define ABYTES   (128 * 64 * 2)
#define STAGEB   (2 * ABYTES)
#define NKCHUNK  16
#define GEMM_DSMEM (NSTAGE * STAGEB + 1024)

template <bool HALF_OUT>
__global__ __launch_bounds__(256, 2)
void gemm_tma_kernel(const __grid_constant__ CUtensorMap tmA,
                     const __grid_constant__ CUtensorMap tmW,
                     const float* __restrict__ bias,
                     void* __restrict__ Cc, int N)
{
    extern __shared__ char dsm_raw[];
    __shared__ __align__(8) unsigned long long s_mbar[2 * NSTAGE];

    char* smb = (char*)(((uintptr_t)dsm_raw + 1023) & ~(uintptr_t)1023);
    const unsigned base = sptr(smb);

    const int tid  = threadIdx.x;
    const int warp = tid >> 5;
    const int lane = tid & 31;
    const int wm   = warp & 3;
    const int wn   = warp >> 2;
    const int g    = lane >> 2;
    const int q    = lane & 3;
    const int la   = lane & 7;
    const int lb   = (lane >> 3) & 1;
    const int lc   = lane >> 4;
    const int bm   = blockIdx.y * 128;
    const int bn   = blockIdx.x * 128;

    unsigned mf[NSTAGE], me[NSTAGE];
#pragma unroll
    for (int s = 0; s < NSTAGE; s++) {
        mf[s] = sptr(&s_mbar[s]);
        me[s] = sptr(&s_mbar[NSTAGE + s]);
    }

    if (tid == 0) {
#pragma unroll
        for (int s = 0; s < NSTAGE; s++) {
            mbar_init(mf[s], 1);
            mbar_init(me[s], 8);
        }
    }
    __syncthreads();

    if (tid == 0) {
#pragma unroll
        for (int s = 0; s < NSTAGE; s++) {
            mbar_expect(mf[s], STAGEB);
            tma3d(base + s * STAGEB,          &tmA, s * 64, bm, mf[s]);
            tma3d(base + s * STAGEB + ABYTES, &tmW, s * 64, bn, mf[s]);
        }
    }

    float acc[2][8][4];
#pragma unroll
    for (int mt = 0; mt < 2; mt++)
#pragma unroll
        for (int nt = 0; nt < 8; nt++)
#pragma unroll
            for (int c = 0; c < 4; c++) acc[mt][nt][c] = 0.0f;

    for (int c = 0; c < NKCHUNK; c++) {
        const int s = c % NSTAGE;
        const unsigned ph = (unsigned)((c / NSTAGE) & 1);
        mbar_wait(mf[s], ph);

        const unsigned abase = base + s * STAGEB;
        const unsigned bbase = abase + ABYTES;

#pragma unroll
        for (int kk = 0; kk < 4; kk++) {
            unsigned a[2][4];
#pragma unroll
            for (int mt = 0; mt < 2; mt++) {
                int row = wm * 32 + mt * 16 + lb * 8 + la;
                int ch  = (2 * kk + lc) ^ (row & 7);
                ldsm4(a[mt][0], a[mt][1], a[mt][2], a[mt][3],
                      abase + row * 128 + ch * 16);
            }
            unsigned bfr[4][4];
#pragma unroll
            for (int ntp = 0; ntp < 4; ntp++) {
                int row = wn * 64 + ntp * 16 + lc * 8 + la;
                int ch  = (2 * kk + lb) ^ (row & 7);
                ldsm4(bfr[ntp][0], bfr[ntp][1], bfr[ntp][2], bfr[ntp][3],
                      bbase + row * 128 + ch * 16);
            }
#pragma unroll
            for (int mt = 0; mt < 2; mt++)
#pragma unroll
                for (int ntp = 0; ntp < 4; ntp++) {
                    mma16816(acc[mt][2 * ntp],     a[mt][0], a[mt][1], a[mt][2], a[mt][3],
                             bfr[ntp][0], bfr[ntp][1]);
                    mma16816(acc[mt][2 * ntp + 1], a[mt][0], a[mt][1], a[mt][2], a[mt][3],
                             bfr[ntp][2], bfr[ntp][3]);
                }
        }

        if (lane == 0) mbar_arrive(me[s]);

        if (warp == (c & 7) && lane == 0) {
            const int cn = c + NSTAGE;
            if (cn < NKCHUNK) {
                mbar_wait(me[s], ph);
                fence_async_shared();
                mbar_expect(mf[s], STAGEB);
                tma3d(abase, &tmA, cn * 64, bm, mf[s]);
                tma3d(bbase, &tmW, cn * 64, bn, mf[s]);
            }
        }
    }

    float2 bv[8];
#pragma unroll
    for (int nt = 0; nt < 8; nt++) {
        int col = bn + wn * 64 + nt * 8 + 2 * q;
        bv[nt].x = bias[col];
        bv[nt].y = bias[col + 1];
    }
#pragma unroll
    for (int mt = 0; mt < 2; mt++) {
        int row = bm + wm * 32 + mt * 16 + g;
#pragma unroll
        for (int nt = 0; nt < 8; nt++) {
            int col = bn + wn * 64 + nt * 8 + 2 * q;
            float x0 = acc[mt][nt][0] + bv[nt].x;
            float y0 = acc[mt][nt][1] + bv[nt].y;
            float x1 = acc[mt][nt][2] + bv[nt].x;
            float y1 = acc[mt][nt][3] + bv[nt].y;
            if (HALF_OUT) {
                __half* O = (__half*)Cc;
                *(__half2*)&O[(size_t)row * N + col]       = __floats2half2_rn(x0, y0);
                *(__half2*)&O[(size_t)(row + 8) * N + col] = __floats2half2_rn(x1, y1);
            } else {
                float* O = (float*)Cc;
                *(float2*)&O[(size_t)row * N + col]       = make_float2(x0, y0);
                *(float2*)&O[(size_t)(row + 8) * N + col] = make_float2(x1, y1);
            }
        }
    }
}

// ---------------------------------------------------------------------------
// Flash attention: FA2 register pipeline, free-running warps, split K/V
// barriers, exp2 softmax (ex2.approx), hoisted Q frags, rotating producer.
// Round 14: lane-local l (end-of-loop reduce), conditional o-rescale.
// ---------------------------------------------------------------------------
#define FSTR 72
#define FL_TILEB  (64 * 64 * 2)                    // 8 KB
#define FL_QB     (64 * FSTR * 2)                  // 9 KB
#define FL_DSMEM  (4 * FL_TILEB + FL_QB + 1024)
#define QSCALE_LOG2E 0.1803368801111f              // 0.125 * log2(e)

__global__ __launch_bounds__(128, 4)
void flash_f16_kernel(const __grid_constant__ CUtensorMap tmKV,
                      const __half* __restrict__ qkv, __half* __restrict__ out)
{
    extern __shared__ char fraw[];
    __shared__ __align__(8) unsigned long long s_fmk[2];
    __shared__ __align__(8) unsigned long long s_fmv[2];
    __shared__ __align__(8) unsigned long long s_fe[2];

    char* fb = (char*)(((uintptr_t)fraw + 1023) & ~(uintptr_t)1023);
    const unsigned base = sptr(fb);
    const unsigned kbuf[2] = {base,                base + FL_TILEB};
    const unsigned vbuf[2] = {base + 2 * FL_TILEB, base + 3 * FL_TILEB};
    __half* Qs = (__half*)(fb + 4 * FL_TILEB);
    const unsigned qsb = sptr(Qs);
    const unsigned fmk[2] = {sptr(&s_fmk[0]), sptr(&s_fmk[1])};
    const unsigned fmv[2] = {sptr(&s_fmv[0]), sptr(&s_fmv[1])};
    const unsigned fe[2]  = {sptr(&s_fe[0]),  sptr(&s_fe[1])};

    const int qt   = (int)gridDim.x - 1 - (int)blockIdx.x;  // heavy tiles first
    const int bh   = blockIdx.y;
    const int bb   = bh >> 4;
    const int h    = bh & 15;
    const int tid  = threadIdx.x;
    const int warp = tid >> 5;
    const int lane = tid & 31;
    const int g    = lane >> 2;
    const int q    = lane & 3;
    const int la   = lane & 7;
    const int lb   = (lane >> 3) & 1;
    const int lc   = lane >> 4;
    const int r0   = warp * 16 + g;
    const int r1   = r0 + 8;

    if (tid == 0) {
        mbar_init(fmk[0], 1); mbar_init(fmk[1], 1);
        mbar_init(fmv[0], 1); mbar_init(fmv[1], 1);
        mbar_init(fe[0], 4);  mbar_init(fe[1], 4);
    }

    // Load Q tile (scaled by 0.125*log2e -> exp2-domain scores)
    const __half* qb = qkv + (size_t)(bb * T_) * N_QKV + h * D_;
    const __half2 hs = __floats2half2_rn(QSCALE_LOG2E, QSCALE_LOG2E);
#pragma unroll
    for (int i = 0; i < 4; i++) {
        int idx = tid + i * 128;
        int r   = idx >> 3;
        int c8  = idx & 7;
        uint4 v = *(const uint4*)(qb + (size_t)(qt * 64 + r) * N_QKV + 8 * c8);
        __half2* p = (__half2*)&v;
        p[0] = __hmul2(p[0], hs); p[1] = __hmul2(p[1], hs);
        p[2] = __hmul2(p[2], hs); p[3] = __hmul2(p[3], hs);
        *(uint4*)&Qs[r * FSTR + 8 * c8] = v;
    }
    __syncthreads();   // mbar init + Q stores visible

    if (tid == 0) {
        mbar_expect(fmk[0], FL_TILEB);
        tma3d(kbuf[0], &tmKV, C_ + h * 64,     bb * T_, fmk[0]);
        mbar_expect(fmv[0], FL_TILEB);
        tma3d(vbuf[0], &tmKV, 2 * C_ + h * 64, bb * T_, fmv[0]);
    }

    // Hoist Q fragments (iteration-invariant)
    unsigned qa[4][4];
#pragma unroll
    for (int kk = 0; kk < 4; kk++) {
        int row = warp * 16 + lb * 8 + la;
        int ch  = 2 * kk + lc;
        ldsm4(qa[kk][0], qa[kk][1], qa[kk][2], qa[kk][3],
              qsb + (row * FSTR + ch * 8) * 2);
    }

    float o[8][4];
#pragma unroll
    for (int j = 0; j < 8; j++)
#pragma unroll
        for (int c = 0; c < 4; c++) o[j][c] = 0.0f;
    float m0 = -1e30f, m1 = -1e30f;
    float l0 = 0.0f, l1 = 0.0f;    // lane-local partials (16 cols each)

    for (int kt = 0; kt <= qt; kt++) {
        const int buf = kt & 1;
        const unsigned ph = (unsigned)((kt >> 1) & 1);

        // Rotating producer: prefetch kt+1 (depends only on fe[nb]).
        if (warp == (kt & 3) && lane == 0 && kt < qt) {
            const int nb = buf ^ 1;
            if (kt > 0) mbar_wait(fe[nb], (unsigned)(((kt - 1) >> 1) & 1));
            fence_async_shared();
            mbar_expect(fmk[nb], FL_TILEB);
            tma3d(kbuf[nb], &tmKV, C_ + h * 64,     bb * T_ + (kt + 1) * 64, fmk[nb]);
            mbar_expect(fmv[nb], FL_TILEB);
            tma3d(vbuf[nb], &tmKV, 2 * C_ + h * 64, bb * T_ + (kt + 1) * 64, fmv[nb]);
        }

        mbar_wait(fmk[buf], ph);

        // ---- S = Q K^T (exp2 domain)
        float s[8][4];
#pragma unroll
        for (int j = 0; j < 8; j++)
#pragma unroll
            for (int c = 0; c < 4; c++) s[j][c] = 0.0f;

#pragma unroll
        for (int kk = 0; kk < 4; kk++) {
#pragma unroll
            for (int ntp = 0; ntp < 4; ntp++) {
                unsigned b0, b1, b2, b3;
                int row = ntp * 16 + lc * 8 + la;
                int ch  = (2 * kk + lb) ^ (row & 7);
                ldsm4(b0, b1, b2, b3, kbuf[buf] + row * 128 + ch * 16);
                mma16816(s[2 * ntp],     qa[kk][0], qa[kk][1], qa[kk][2], qa[kk][3], b0, b1);
                mma16816(s[2 * ntp + 1], qa[kk][0], qa[kk][1], qa[kk][2], qa[kk][3], b2, b3);
            }
        }

        // Causal mask (diagonal tile only)
        if (kt == qt) {
#pragma unroll
            for (int j = 0; j < 8; j++) {
                int c = j * 8 + 2 * q;
                if (c     > r0) s[j][0] = -1e30f;
                if (c + 1 > r0) s[j][1] = -1e30f;
                if (c     > r1) s[j][2] = -1e30f;
                if (c + 1 > r1) s[j][3] = -1e30f;
            }
        }

        // ---- In-warp online softmax (exp2 domain)
        float mx0 = -1e30f, mx1 = -1e30f;
#pragma unroll
        for (int j = 0; j < 8; j++) {
            mx0 = fmaxf(mx0, fmaxf(s[j][0], s[j][1]));
            mx1 = fmaxf(mx1, fmaxf(s[j][2], s[j][3]));
        }
        mx0 = fmaxf(mx0, __shfl_xor_sync(0xffffffffu, mx0, 1));
        mx0 = fmaxf(mx0, __shfl_xor_sync(0xffffffffu, mx0, 2));
        mx1 = fmaxf(mx1, __shfl_xor_sync(0xffffffffu, mx1, 1));
        mx1 = fmaxf(mx1, __shfl_xor_sync(0xffffffffu, mx1, 2));

        float mn0 = fmaxf(m0, mx0);
        float mn1 = fmaxf(m1, mx1);
        const bool upd = (mn0 != m0) | (mn1 != m1);
        float cr0 = ex2(m0 - mn0);
        float cr1 = ex2(m1 - mn1);
        m0 = mn0; m1 = mn1;

        float sum0 = 0.0f, sum1 = 0.0f;
        unsigned plo[8], phi[8];
#pragma unroll
        for (int j = 0; j < 8; j++) {
            float p0 = ex2(s[j][0] - mn0);
            float p1 = ex2(s[j][1] - mn0);
            float p2 = ex2(s[j][2] - mn1);
            float p3 = ex2(s[j][3] - mn1);
            sum0 += p0 + p1;
            sum1 += p2 + p3;
            plo[j] = packh2(p0, p1);
            phi[j] = packh2(p2, p3);
        }
        // lane-local l update (row reduction deferred to epilogue)
        l0 = l0 * cr0 + sum0;
        l1 = l1 * cr1 + sum1;

        // o-rescale only when some row max actually changed (warp-uniform)
        if (__any_sync(0xffffffffu, upd)) {
#pragma unroll
            for (int j = 0; j < 8; j++) {
                o[j][0] *= cr0; o[j][1] *= cr0;
                o[j][2] *= cr1; o[j][3] *= cr1;
            }
        }

        // ---- O += P V (wait for V arrival first)
        mbar_wait(fmv[buf], ph);
#pragma unroll
        for (int t = 0; t < 4; t++) {
            const unsigned a0 = plo[2 * t];
            const unsigned a1 = phi[2 * t];
            const unsigned a2 = plo[2 * t + 1];
            const unsigned a3 = phi[2 * t + 1];
#pragma unroll
            for (int ntp = 0; ntp < 4; ntp++) {
                unsigned b0, b1, b2, b3;
                int row = t * 16 + lb * 8 + la;
                int ch  = (2 * ntp + lc) ^ (row & 7);
                ldsm4t(b0, b1, b2, b3, vbuf[buf] + row * 128 + ch * 16);
                mma16816(o[2 * ntp],     a0, a1, a2, a3, b0, b1);
                mma16816(o[2 * ntp + 1], a0, a1, a2, a3, b2, b3);
            }
        }

        if (lane == 0) mbar_arrive(fe[buf]);
    }

    // Epilogue: single row reduction of l, then normalize + store
    l0 += __shfl_xor_sync(0xffffffffu, l0, 1);
    l0 += __shfl_xor_sync(0xffffffffu, l0, 2);
    l1 += __shfl_xor_sync(0xffffffffu, l1, 1);
    l1 += __shfl_xor_sync(0xffffffffu, l1, 2);
    float il0 = 1.0f / l0;
    float il1 = 1.0f / l1;
    size_t row0 = (size_t)(bb * T_ + qt * 64 + r0);
    size_t row1 = (size_t)(bb * T_ + qt * 64 + r1);
#pragma unroll
    for (int j = 0; j < 8; j++) {
        int col = h * 64 + j * 8 + 2 * q;
        *(__half2*)&out[row0 * C_ + col] = __floats2half2_rn(o[j][0] * il0, o[j][1] * il0);
        *(__half2*)&out[row1 * C_ + col] = __floats2half2_rn(o[j][2] * il1, o[j][3] * il1);
    }
}

// ---------------------------------------------------------------------------
// Host: tensormaps + launch
// ---------------------------------------------------------------------------
typedef CUresult (*PFN_encode)(CUtensorMap*, CUtensorMapDataType, cuuint32_t, void*,
                               const cuuint64_t*, const cuuint64_t*, const cuuint32_t*,
                               const cuuint32_t*, CUtensorMapInterleave, CUtensorMapSwizzle,
                               CUtensorMapL2promotion, CUtensorMapFloatOOBfill);

static void make_map(PFN_encode enc, CUtensorMap* tm, void* ptr,
                     unsigned long long cols, unsigned long long rows,
                     unsigned bx, unsigned by) {
    cuuint64_t dims[3]    = {cols, rows, 1};
    cuuint64_t strides[2] = {cols * 2, rows * cols * 2};
    cuuint32_t box[3]     = {bx, by, 1};
    cuuint32_t es[3]      = {1, 1, 1};
    enc(tm, CU_TENSOR_MAP_DATA_TYPE_FLOAT16, 3, ptr, dims, strides, box, es,
        CU_TENSOR_MAP_INTERLEAVE_NONE, CU_TENSOR_MAP_SWIZZLE_128B,
        CU_TENSOR_MAP_L2_PROMOTION_L2_128B, CU_TENSOR_MAP_FLOAT_OOB_FILL_NONE);
}

extern "C" void kernel_launch(void* const* d_in, const int* in_sizes, int n_in,
                              void* d_out, int out_size)
{
    const float* x      = (const float*)d_in[0];
    const float* W_qkv  = (const float*)d_in[1];
    const float* b_qkv  = (const float*)d_in[2];
    const float* W_proj = (const float*)d_in[3];
    const float* b_proj = (const float*)d_in[4];
    float* out = (float*)d_out;

    __half *hx, *hw1, *hw2, *qkv, *att;
    cudaGetSymbolAddress((void**)&hx,  g_hx);
    cudaGetSymbolAddress((void**)&hw1, g_hw1);
    cudaGetSymbolAddress((void**)&hw2, g_hw2);
    cudaGetSymbolAddress((void**)&qkv, g_qkv);
    cudaGetSymbolAddress((void**)&att, g_att);

    void* fnp = nullptr;
    cudaDriverEntryPointQueryResult qr;
    cudaGetDriverEntryPointByVersion("cuTensorMapEncodeTiled", &fnp, 12000,
                                     cudaEnableDefault, &qr);
    PFN_encode enc = (PFN_encode)fnp;

    CUtensorMap tmX, tmW1, tmAtt, tmW2, tmKV;
    make_map(enc, &tmX,   hx,  C_,    M_,    64, 128);
    make_map(enc, &tmW1,  hw1, C_,    N_QKV, 64, 128);
    make_map(enc, &tmAtt, att, C_,    M_,    64, 128);
    make_map(enc, &tmW2,  hw2, C_,    C_,    64, 128);
    make_map(enc, &tmKV,  qkv, N_QKV, M_,    64, 64);

    // 0) fused fp32 -> fp16 converts (single launch)
    f2h_all_kernel<<<(CVT_TOTAL + 255) / 256, 256>>>(x, W_qkv, W_proj, hx, hw1, hw2);

    // 1) qkv = x @ W_qkv^T + b_qkv (half out)
    cudaFuncSetAttribute((const void*)gemm_tma_kernel<true>,
                         cudaFuncAttributeMaxDynamicSharedMemorySize, GEMM_DSMEM);
    gemm_tma_kernel<true><<<dim3(N_QKV / 128, M_ / 128), 256, GEMM_DSMEM>>>(
        tmX, tmW1, b_qkv, qkv, N_QKV);

    // 2) flash attention
    cudaFuncSetAttribute(flash_f16_kernel,
                         cudaFuncAttributeMaxDynamicSharedMemorySize, FL_DSMEM);
    flash_f16_kernel<<<dim3(T_ / 64, B_ * H_), 128, FL_DSMEM>>>(tmKV, qkv, att);

    // 3) out = att @ W_proj^T + b_proj (float out)
    cudaFuncSetAttribute((const void*)gemm_tma_kernel<false>,
                         cudaFuncAttributeMaxDynamicSharedMemorySize, GEMM_DSMEM);
    gemm_tma_kernel<false><<<dim3(C_ / 128, M_ / 128), 256, GEMM_DSMEM>>>(
        tmAtt, tmW2, b_proj, out, C_);
}